// round 7
// baseline (speedup 1.0000x reference)
#include <cuda_runtime.h>
#include <cuda_fp16.h>
#include <math.h>
#include <stdint.h>

#define B_  2
#define S_  2048
#define DM_ 2048
#define H_  16
#define DH_ 128
#define NQKV 2304   // 2048 q + 128 k + 128 v

// ---------------- scratch (device globals: allocation-free) ----------------
__device__ __half g_Xh[B_*S_*DM_];
__device__ __half g_Wqkvh[NQKV*DM_];       // rows: 0..2047 Wq, 2048..2175 Wk, 2176..2303 Wv
__device__ __half g_Wph[DM_*DM_];
__device__ __half g_Qh[B_*H_*S_*DH_];      // [B,H,S,D]  (scaled by sw*log2e)
__device__ __half g_Kh[B_*S_*DH_];         // [B,S,D]    (scaled by sw)
__device__ __half g_Vt[B_*DH_*S_];         // [B,D,S]
__device__ __half g_ctxh[B_*S_*DM_];
__device__ float  g_qc[S_*64], g_qs[S_*64], g_kc[S_*64], g_ks[S_*64];

// ---------------- helpers ----------------
__device__ __forceinline__ void mma_h(float c[4], const unsigned a[4], const unsigned b[2]) {
    asm volatile(
        "mma.sync.aligned.m16n8k16.row.col.f32.f16.f16.f32 "
        "{%0,%1,%2,%3},{%4,%5,%6,%7},{%8,%9},{%0,%1,%2,%3};"
        : "+f"(c[0]), "+f"(c[1]), "+f"(c[2]), "+f"(c[3])
        : "r"(a[0]), "r"(a[1]), "r"(a[2]), "r"(a[3]), "r"(b[0]), "r"(b[1]));
}
__device__ __forceinline__ void cpasync16(void* s, const void* g) {
    unsigned sa = (unsigned)__cvta_generic_to_shared(s);
    asm volatile("cp.async.cg.shared.global [%0], [%1], 16;" :: "r"(sa), "l"(g));
}
#define CP_COMMIT() asm volatile("cp.async.commit_group;" ::: "memory")
#define CP_WAIT(n)  asm volatile("cp.async.wait_group %0;" :: "n"(n) : "memory")
__device__ __forceinline__ unsigned packh2(float x, float y) {
    __half2 h = __floats2half2_rn(x, y);
    return *(unsigned*)&h;
}

// ---------------- fp32 -> fp16 convert, all four tensors in one launch -----
#define N4_X  (B_*S_*DM_/4)
#define N4_WQ (DM_*DM_/4)
#define N4_WKV (2*DH_*DM_/4)
#define N4_WP (DM_*DM_/4)
#define N4_TOT (N4_X + N4_WQ + N4_WKV + N4_WP)

__global__ void cvt_all(const float4* __restrict__ X, const float4* __restrict__ Wq,
                        const float4* __restrict__ Wkv, const float4* __restrict__ Wp) {
    int i = blockIdx.x*1024 + threadIdx.x;
    #pragma unroll
    for (int k = 0; k < 4; k++) {
        int j = i + k*256;
        if (j >= N4_TOT) return;
        const float4* src; __half2* dst; int off;
        if (j < N4_X) {
            src = X; dst = (__half2*)g_Xh; off = j;
        } else if (j < N4_X + N4_WQ) {
            src = Wq; dst = (__half2*)g_Wqkvh; off = j - N4_X;
        } else if (j < N4_X + N4_WQ + N4_WKV) {
            src = Wkv; dst = (__half2*)(g_Wqkvh + (size_t)DM_*DM_); off = j - N4_X - N4_WQ;
        } else {
            src = Wp; dst = (__half2*)g_Wph; off = j - N4_X - N4_WQ - N4_WKV;
        }
        float4 v = src[off];
        dst[2*off]   = __floats2half2_rn(v.x, v.y);
        dst[2*off+1] = __floats2half2_rn(v.z, v.w);
    }
}

// ---------------- rotary tables ----------------
__global__ void rotary_tables() {
    int idx = blockIdx.x*blockDim.x + threadIdx.x;
    if (idx >= S_*64) return;
    int s = idx >> 6, j = idx & 63;
    float inv_freq = powf(10000.0f, -(2.0f*j)/128.0f);
    float pos = (float)s * inv_freq;
    float sb = (2.0f*j + 0.4f*128.0f) / (1.4f*128.0f);
    float power = ((float)s - (float)(S_/2)) / 512.0f;
    float xs = powf(sb, power);
    float c = cosf(pos), sn = sinf(pos);
    g_qc[idx] = c*xs;  g_qs[idx] = sn*xs;
    g_kc[idx] = c/xs;  g_ks[idx] = sn/xs;
}

// ========== shared GEMM mainloop macro: CTA 128x256, BK=32, 3-stage =========
#define ASTG_H (128*72)
#define BSTG_H (256*72)
#define STG_H  (ASTG_H + BSTG_H)
#define G_SMEM (3*STG_H*2)

#define GEMM_MAINLOOP(A, Bm, K)                                               \
    float acc[4][8][4];                                                       \
    _Pragma("unroll")                                                         \
    for (int i=0;i<4;i++)                                                     \
        _Pragma("unroll")                                                     \
        for (int j=0;j<8;j++)                                                 \
            _Pragma("unroll")                                                 \
            for (int k=0;k<4;k++) acc[i][j][k]=0.f;                           \
    LOAD_TILE(0, 0);  CP_COMMIT();                                            \
    LOAD_TILE(1, 32); CP_COMMIT();                                            \
    int T = (K) >> 5;                                                         \
    int stg = 0;                                                              \
    for (int tt = 0; tt < T; tt++) {                                          \
        if (tt == T-1) { CP_WAIT(0); } else { CP_WAIT(1); }                   \
        __syncthreads();                                                      \
        if (tt+2 < T) {                                                       \
            int sn = stg+2; if (sn >= 3) sn -= 3;                             \
            LOAD_TILE(sn, (tt+2)*32);                                         \
            CP_COMMIT();                                                      \
        }                                                                     \
        const __half* As = smh + stg*STG_H;                                   \
        const __half* Bs = As + ASTG_H;                                       \
        _Pragma("unroll")                                                     \
        for (int kb = 0; kb < 2; kb++) {                                      \
            unsigned af[4][4], bf[8][2];                                      \
            int co = kb*16 + 2*t;                                             \
            _Pragma("unroll")                                                 \
            for (int mf = 0; mf < 4; mf++) {                                  \
                int r = wm + mf*16 + g;                                       \
                af[mf][0] = *(const unsigned*)&As[r*72 + co];                 \
                af[mf][1] = *(const unsigned*)&As[(r+8)*72 + co];             \
                af[mf][2] = *(const unsigned*)&As[r*72 + co + 8];             \
                af[mf][3] = *(const unsigned*)&As[(r+8)*72 + co + 8];         \
            }                                                                 \
            _Pragma("unroll")                                                 \
            for (int nf = 0; nf < 8; nf++) {                                  \
                int rn = wn + nf*8 + g;                                       \
                bf[nf][0] = *(const unsigned*)&Bs[rn*72 + co];                \
                bf[nf][1] = *(const unsigned*)&Bs[rn*72 + co + 8];            \
            }                                                                 \
            _Pragma("unroll")                                                 \
            for (int mf = 0; mf < 4; mf++)                                    \
                _Pragma("unroll")                                             \
                for (int nf = 0; nf < 8; nf++)                                \
                    mma_h(acc[mf][nf], af[mf], bf[nf]);                       \
        }                                                                     \
        if (++stg >= 3) stg = 0;                                              \
    }

#define LOAD_TILE(stg, k0) do {                                               \
    __half* sA = smh + (stg)*STG_H;                                           \
    __half* sB = sA + ASTG_H;                                                 \
    _Pragma("unroll")                                                         \
    for (int it = 0; it < 2; it++) {                                          \
        int idx = tid + it*256;                                               \
        int r = idx >> 2, c = idx & 3;                                        \
        cpasync16(&sA[r*72 + c*8], &A[(size_t)(m0+r)*K_ + (k0) + c*8]);       \
    }                                                                         \
    _Pragma("unroll")                                                         \
    for (int it = 0; it < 4; it++) {                                          \
        int idx = tid + it*256;                                               \
        int r = idx >> 2, c = idx & 3;                                        \
        cpasync16(&sB[r*72 + c*8], &Bm[(size_t)(n0+r)*K_ + (k0) + c*8]);      \
    }                                                                         \
} while (0)

// ========== QKV GEMM with fused rotary/transpose epilogue ===================
// grid (9, 32): bx 0..7 -> Q heads, bx 8 -> K (cols 0..127) + V (cols 128..255)
#define ESTR 264

__global__ __launch_bounds__(256) void gemm_qkv() {
    extern __shared__ __half smh[];
    const __half* A  = g_Xh;
    const __half* Bm = g_Wqkvh;
    const int K_ = DM_;
    int tid = threadIdx.x, wid = tid >> 5, lane = tid & 31;
    int g = lane >> 2, t = lane & 3;
    int wm = (wid & 1)*64, wn = (wid >> 1)*64;
    int m0 = blockIdx.y*128, n0 = blockIdx.x*256;

    GEMM_MAINLOOP(A, Bm, K_)

    // ---- stage fp32 tile to smem ----
    __syncthreads();
    float* Es = (float*)smh;
    #pragma unroll
    for (int mf = 0; mf < 4; mf++) {
        #pragma unroll
        for (int nf = 0; nf < 8; nf++) {
            int row = wm + mf*16 + g;
            int col = wn + nf*8 + 2*t;
            *(float2*)&Es[row*ESTR + col]     = make_float2(acc[mf][nf][0], acc[mf][nf][1]);
            *(float2*)&Es[(row+8)*ESTR + col] = make_float2(acc[mf][nf][2], acc[mf][nf][3]);
        }
    }
    __syncthreads();

    int bb = m0 >> 11;           // batch (tile of 128 rows never crosses batch)
    int sbase = m0 & (S_-1);

    if (n0 < 2048) {
        // Q: rotary (xs scale), folded sw*log2e, layout [B,H,S,D]
        const float swq = 0.08838834764831845f * 1.4426950408889634f;
        int d = tid & 63, rh = tid >> 6;       // rh 0..3
        #pragma unroll 2
        for (int hh = 0; hh < 2; hh++) {
            int h = (n0 >> 7) + hh;
            size_t obase = (size_t)(bb*H_ + h) * S_;
            for (int it = 0; it < 32; it++) {
                int r = rh + it*4;
                float x1 = Es[r*ESTR + hh*128 + d];
                float x2 = Es[r*ESTR + hh*128 + d + 64];
                int s = sbase + r;
                float c = g_qc[s*64+d], sn = g_qs[s*64+d];
                size_t ob = (obase + s)*DH_;
                g_Qh[ob + d]      = __float2half_rn(swq*(x1*c - x2*sn));
                g_Qh[ob + d + 64] = __float2half_rn(swq*(x2*c + x1*sn));
            }
        }
    } else {
        // K: rotary (1/xs scale), folded sw, layout [B,S,D]
        const float sw = 0.08838834764831845f;
        int d = tid & 63, rh = tid >> 6;
        for (int it = 0; it < 32; it++) {
            int r = rh + it*4;
            float x1 = Es[r*ESTR + d];
            float x2 = Es[r*ESTR + d + 64];
            int s = sbase + r;
            float c = g_kc[s*64+d], sn = g_ks[s*64+d];
            size_t ob = ((size_t)(bb*S_ + s))*DH_;
            g_Kh[ob + d]      = __float2half_rn(sw*(x1*c - x2*sn));
            g_Kh[ob + d + 64] = __float2half_rn(sw*(x2*c + x1*sn));
        }
        // V: transpose to [B,D,S]
        int r = tid & 127, dh = tid >> 7;      // dh 0..1
        for (int d2 = 0; d2 < 64; d2++) {
            int d = dh*64 + d2;
            g_Vt[((size_t)(bb*DH_ + d))*S_ + sbase + r] =
                __float2half_rn(Es[r*ESTR + 128 + d]);
        }
    }
}

// ========== proj GEMM: out(f32) = ctx @ Wp^T + bias =========================
__global__ __launch_bounds__(256) void gemm_h(
        const __half* __restrict__ A, const __half* __restrict__ Bm,
        float* __restrict__ C, int M, int N, int K_,
        const float* __restrict__ bias) {
    extern __shared__ __half smh[];
    int tid = threadIdx.x, wid = tid >> 5, lane = tid & 31;
    int g = lane >> 2, t = lane & 3;
    int wm = (wid & 1)*64, wn = (wid >> 1)*64;
    int m0 = blockIdx.y*128, n0 = blockIdx.x*256;

    GEMM_MAINLOOP(A, Bm, K_)

    #pragma unroll
    for (int mf = 0; mf < 4; mf++) {
        #pragma unroll
        for (int nf = 0; nf < 8; nf++) {
            int row = m0 + wm + mf*16 + g;
            int col = n0 + wn + nf*8 + 2*t;
            float b0 = bias[col], b1 = bias[col+1];
            *(float2*)&C[(size_t)row*N + col] =
                make_float2(acc[mf][nf][0]+b0, acc[mf][nf][1]+b1);
            *(float2*)&C[(size_t)(row+8)*N + col] =
                make_float2(acc[mf][nf][2]+b0, acc[mf][nf][3]+b1);
        }
    }
}

// ---------------- flash attention (fp16 mma, BQ=128, BKV=128) --------------
#define KS_H (128*136)
#define VS_H (128*136)
#define FSTG_H (KS_H + VS_H)
#define FL_SMEM (2*FSTG_H*2)

__global__ __launch_bounds__(256) void flash_attn() {
    extern __shared__ __half smf[];
    int tid = threadIdx.x;
    int wid = tid >> 5, lane = tid & 31;
    int g = lane >> 2, t = lane & 3;
    int bh = blockIdx.y, b = bh >> 4, h = bh & 15;
    int qt = gridDim.x - 1 - blockIdx.x;   // longest work first
    int q0 = qt * 128;
    int wrow = wid * 16;
    const __half* Qb  = g_Qh + (size_t)bh * S_ * DH_;
    const __half* Kb  = g_Kh + (size_t)b  * S_ * DH_;
    const __half* Vtb = g_Vt + (size_t)b  * DH_ * S_;

    unsigned qa[8][4];
    {
        int r0 = q0 + wrow + g;
        #pragma unroll
        for (int kb = 0; kb < 8; kb++) {
            int c0 = kb*16 + 2*t;
            qa[kb][0] = *(const unsigned*)&Qb[(size_t)r0*DH_ + c0];
            qa[kb][1] = *(const unsigned*)&Qb[(size_t)(r0+8)*DH_ + c0];
            qa[kb][2] = *(const unsigned*)&Qb[(size_t)r0*DH_ + c0 + 8];
            qa[kb][3] = *(const unsigned*)&Qb[(size_t)(r0+8)*DH_ + c0 + 8];
        }
    }
    float oacc[16][4];
    #pragma unroll
    for (int i=0;i<16;i++)
        #pragma unroll
        for (int j=0;j<4;j++) oacc[i][j]=0.f;
    float mrow[2] = {-1e30f,-1e30f}, lrow[2] = {0.f,0.f};

    int ntiles = qt + 1;
    #define LOAD_KV(stg, j0) do {                                             \
        __half* Ks_ = smf + (stg)*FSTG_H;                                     \
        __half* Vs_ = Ks_ + KS_H;                                             \
        _Pragma("unroll")                                                     \
        for (int it = 0; it < 8; it++) {                                      \
            int idx = tid + it*256;                                           \
            int r = idx >> 4, c = idx & 15;                                   \
            cpasync16(&Ks_[r*136 + c*8], &Kb[(size_t)((j0)+r)*DH_ + c*8]);    \
        }                                                                     \
        _Pragma("unroll")                                                     \
        for (int it = 0; it < 8; it++) {                                      \
            int idx = tid + it*256;                                           \
            int r = idx >> 4, c = idx & 15;                                   \
            cpasync16(&Vs_[r*136 + c*8], &Vtb[(size_t)r*S_ + (j0) + c*8]);    \
        }                                                                     \
    } while (0)

    LOAD_KV(0, 0);
    CP_COMMIT();

    for (int kt = 0; kt < ntiles; kt++) {
        if (kt+1 < ntiles) {
            LOAD_KV((kt+1)&1, (kt+1)*128);
            CP_COMMIT();
            CP_WAIT(1);
        } else {
            CP_WAIT(0);
        }
        __syncthreads();
        const __half* Ks = smf + (kt&1)*FSTG_H;
        const __half* Vs = Ks + KS_H;
        int j0 = kt * 128;

        float s[16][4];
        #pragma unroll
        for (int i=0;i<16;i++)
            #pragma unroll
            for (int j=0;j<4;j++) s[i][j]=0.f;
        #pragma unroll
        for (int kb = 0; kb < 8; kb++) {
            int co = kb*16 + 2*t;
            #pragma unroll
            for (int nf = 0; nf < 16; nf++) {
                unsigned bfr[2];
                bfr[0] = *(const unsigned*)&Ks[(nf*8+g)*136 + co];
                bfr[1] = *(const unsigned*)&Ks[(nf*8+g)*136 + co + 8];
                mma_h(s[nf], qa[kb], bfr);
            }
        }
        if (kt == ntiles-1) {
            int r0 = q0 + wrow + g;
            #pragma unroll
            for (int nf = 0; nf < 16; nf++) {
                int c0 = j0 + nf*8 + 2*t;
                if (c0   > r0)   s[nf][0] = -1e30f;
                if (c0+1 > r0)   s[nf][1] = -1e30f;
                if (c0   > r0+8) s[nf][2] = -1e30f;
                if (c0+1 > r0+8) s[nf][3] = -1e30f;
            }
        }
        #pragma unroll
        for (int rr = 0; rr < 2; rr++) {
            float mx = -1e30f;
            #pragma unroll
            for (int nf = 0; nf < 16; nf++)
                mx = fmaxf(mx, fmaxf(s[nf][2*rr], s[nf][2*rr+1]));
            mx = fmaxf(mx, __shfl_xor_sync(0xffffffffu, mx, 1));
            mx = fmaxf(mx, __shfl_xor_sync(0xffffffffu, mx, 2));
            float mn = fmaxf(mrow[rr], mx);
            float corr = exp2f(mrow[rr] - mn);
            mrow[rr] = mn;
            float rs = 0.f;
            #pragma unroll
            for (int nf = 0; nf < 16; nf++) {
                float e0 = exp2f(s[nf][2*rr]   - mn);
                float e1 = exp2f(s[nf][2*rr+1] - mn);
                s[nf][2*rr] = e0; s[nf][2*rr+1] = e1;
                rs += e0 + e1;
            }
            rs += __shfl_xor_sync(0xffffffffu, rs, 1);
            rs += __shfl_xor_sync(0xffffffffu, rs, 2);
            lrow[rr] = lrow[rr]*corr + rs;
            #pragma unroll
            for (int nf = 0; nf < 16; nf++) {
                oacc[nf][2*rr]   *= corr;
                oacc[nf][2*rr+1] *= corr;
            }
        }
        #pragma unroll
        for (int kb2 = 0; kb2 < 8; kb2++) {
            unsigned pa[4];
            pa[0] = packh2(s[2*kb2][0],   s[2*kb2][1]);
            pa[1] = packh2(s[2*kb2][2],   s[2*kb2][3]);
            pa[2] = packh2(s[2*kb2+1][0], s[2*kb2+1][1]);
            pa[3] = packh2(s[2*kb2+1][2], s[2*kb2+1][3]);
            int co = kb2*16 + 2*t;
            #pragma unroll
            for (int nf = 0; nf < 16; nf++) {
                unsigned bfr[2];
                bfr[0] = *(const unsigned*)&Vs[(nf*8+g)*136 + co];
                bfr[1] = *(const unsigned*)&Vs[(nf*8+g)*136 + co + 8];
                mma_h(oacc[nf], pa, bfr);
            }
        }
        __syncthreads();
    }
    #pragma unroll
    for (int rr = 0; rr < 2; rr++) {
        float inv = 1.f / lrow[rr];
        int row = q0 + wrow + g + 8*rr;
        size_t base = ((size_t)(b*S_ + row))*DM_ + h*DH_;
        #pragma unroll
        for (int nf = 0; nf < 16; nf++) {
            __half2 hv = __floats2half2_rn(oacc[nf][2*rr]*inv, oacc[nf][2*rr+1]*inv);
            *(__half2*)&g_ctxh[base + nf*8 + 2*t] = hv;
        }
    }
    #undef LOAD_KV
}

// ---------------- launch ----------------
extern "C" void kernel_launch(void* const* d_in, const int* in_sizes, int n_in,
                              void* d_out, int out_size) {
    const float* X     = (const float*)d_in[0];
    const float* Wq    = (const float*)d_in[1];
    const float* Wkv   = (const float*)d_in[2];
    const float* Wproj = (const float*)d_in[3];
    const float* bproj = (const float*)d_in[4];
    float* out = (float*)d_out;

    static int attr_set = 0;
    if (!attr_set) {
        cudaFuncSetAttribute(flash_attn, cudaFuncAttributeMaxDynamicSharedMemorySize, FL_SMEM);
        cudaFuncSetAttribute(gemm_h,     cudaFuncAttributeMaxDynamicSharedMemorySize, G_SMEM);
        cudaFuncSetAttribute(gemm_qkv,   cudaFuncAttributeMaxDynamicSharedMemorySize, G_SMEM);
        attr_set = 1;
    }

    __half* ctxh; cudaGetSymbolAddress((void**)&ctxh, g_ctxh);
    __half* wph;  cudaGetSymbolAddress((void**)&wph,  g_Wph);

    const int M = B_*S_;   // 4096

    rotary_tables<<<(S_*64+255)/256, 256>>>();
    cvt_all<<<(N4_TOT+1023)/1024, 256>>>((const float4*)X, (const float4*)Wq,
                                         (const float4*)Wkv, (const float4*)Wproj);
    gemm_qkv<<<dim3(NQKV/256, M/128), 256, G_SMEM>>>();
    flash_attn<<<dim3(S_/128, B_*H_), 256, FL_SMEM>>>();
    gemm_h<<<dim3(DM_/256, M/128), 256, G_SMEM>>>(ctxh, wph, out, M, DM_, DM_, bproj);
}

// round 8
// speedup vs baseline: 1.0239x; 1.0239x over previous
#include <cuda_runtime.h>
#include <cuda_fp16.h>
#include <math.h>
#include <stdint.h>

#define B_  2
#define S_  2048
#define DM_ 2048
#define H_  16
#define DH_ 128
#define NQKV 2304   // 2048 q + 128 k + 128 v

// ---------------- scratch (device globals: allocation-free) ----------------
__device__ __half g_Xh[B_*S_*DM_];
__device__ __half g_Wqkvh[NQKV*DM_];       // rows: 0..2047 Wq, 2048..2175 Wk, 2176..2303 Wv
__device__ __half g_Wph[DM_*DM_];
__device__ __half g_Qh[B_*H_*S_*DH_];      // [B,H,S,D]  (scaled by sw*log2e)
__device__ __half g_Kh[B_*S_*DH_];         // [B,S,D]    (scaled by sw)
__device__ __half g_Vt[B_*DH_*S_];         // [B,D,S]
__device__ __half g_ctxh[B_*S_*DM_];
__device__ float  g_qc[S_*64], g_qs[S_*64], g_kc[S_*64], g_ks[S_*64];

// ---------------- helpers ----------------
__device__ __forceinline__ void mma_h(float c[4], const unsigned a[4], const unsigned b[2]) {
    asm volatile(
        "mma.sync.aligned.m16n8k16.row.col.f32.f16.f16.f32 "
        "{%0,%1,%2,%3},{%4,%5,%6,%7},{%8,%9},{%0,%1,%2,%3};"
        : "+f"(c[0]), "+f"(c[1]), "+f"(c[2]), "+f"(c[3])
        : "r"(a[0]), "r"(a[1]), "r"(a[2]), "r"(a[3]), "r"(b[0]), "r"(b[1]));
}
__device__ __forceinline__ void cpasync16(void* s, const void* g) {
    unsigned sa = (unsigned)__cvta_generic_to_shared(s);
    asm volatile("cp.async.cg.shared.global [%0], [%1], 16;" :: "r"(sa), "l"(g));
}
#define CP_COMMIT() asm volatile("cp.async.commit_group;" ::: "memory")
#define CP_WAIT(n)  asm volatile("cp.async.wait_group %0;" :: "n"(n) : "memory")
__device__ __forceinline__ unsigned packh2(float x, float y) {
    __half2 h = __floats2half2_rn(x, y);
    return *(unsigned*)&h;
}
__device__ __forceinline__ uint32_t smem_u32(const void* p) {
    return (uint32_t)__cvta_generic_to_shared(p);
}
#define LDSM4(r0,r1,r2,r3, a)                                                 \
    asm volatile("ldmatrix.sync.aligned.m8n8.x4.shared.b16 {%0,%1,%2,%3}, [%4];" \
        : "=r"(r0), "=r"(r1), "=r"(r2), "=r"(r3) : "r"(a))

// ---------------- fp32 -> fp16 convert, all four tensors in one launch -----
#define N4_X  (B_*S_*DM_/4)
#define N4_WQ (DM_*DM_/4)
#define N4_WKV (2*DH_*DM_/4)
#define N4_WP (DM_*DM_/4)
#define N4_TOT (N4_X + N4_WQ + N4_WKV + N4_WP)

__global__ void cvt_all(const float4* __restrict__ X, const float4* __restrict__ Wq,
                        const float4* __restrict__ Wkv, const float4* __restrict__ Wp) {
    int i = blockIdx.x*1024 + threadIdx.x;
    #pragma unroll
    for (int k = 0; k < 4; k++) {
        int j = i + k*256;
        if (j >= N4_TOT) return;
        const float4* src; __half2* dst; int off;
        if (j < N4_X) {
            src = X; dst = (__half2*)g_Xh; off = j;
        } else if (j < N4_X + N4_WQ) {
            src = Wq; dst = (__half2*)g_Wqkvh; off = j - N4_X;
        } else if (j < N4_X + N4_WQ + N4_WKV) {
            src = Wkv; dst = (__half2*)(g_Wqkvh + (size_t)DM_*DM_); off = j - N4_X - N4_WQ;
        } else {
            src = Wp; dst = (__half2*)g_Wph; off = j - N4_X - N4_WQ - N4_WKV;
        }
        float4 v = src[off];
        dst[2*off]   = __floats2half2_rn(v.x, v.y);
        dst[2*off+1] = __floats2half2_rn(v.z, v.w);
    }
}

// ---------------- rotary tables ----------------
__global__ void rotary_tables() {
    int idx = blockIdx.x*blockDim.x + threadIdx.x;
    if (idx >= S_*64) return;
    int s = idx >> 6, j = idx & 63;
    float inv_freq = powf(10000.0f, -(2.0f*j)/128.0f);
    float pos = (float)s * inv_freq;
    float sb = (2.0f*j + 0.4f*128.0f) / (1.4f*128.0f);
    float power = ((float)s - (float)(S_/2)) / 512.0f;
    float xs = powf(sb, power);
    float c = cosf(pos), sn = sinf(pos);
    g_qc[idx] = c*xs;  g_qs[idx] = sn*xs;
    g_kc[idx] = c/xs;  g_ks[idx] = sn/xs;
}

// ========== shared GEMM mainloop macro: CTA 128x256, BK=32, 3-stage =========
// fragment loads via ldmatrix.x4
#define ASTG_H (128*72)
#define BSTG_H (256*72)
#define STG_H  (ASTG_H + BSTG_H)
#define G_SMEM (3*STG_H*2)

#define GEMM_MAINLOOP(A, Bm, K)                                               \
    float acc[4][8][4];                                                       \
    _Pragma("unroll")                                                         \
    for (int i=0;i<4;i++)                                                     \
        _Pragma("unroll")                                                     \
        for (int j=0;j<8;j++)                                                 \
            _Pragma("unroll")                                                 \
            for (int k=0;k<4;k++) acc[i][j][k]=0.f;                           \
    uint32_t smb = smem_u32(smh);                                             \
    /* A-mapping: m0 r0-7/c0, m1 r8-15/c0, m2 r0-7/c8, m3 r8-15/c8 */         \
    uint32_t a_off = ((lane & 15)*72 + (lane >> 4)*8)*2 + (wm*72)*2;          \
    /* B-mapping: m0 n0-7/c0, m1 n0-7/c8, m2 n8-15/c0, m3 n8-15/c8 */         \
    uint32_t b_off = ((((lane >> 4)<<3) + (lane & 7))*72 + ((lane >> 3)&1)*8)*2 \
                     + (wn*72)*2 + ASTG_H*2;                                  \
    LOAD_TILE(0, 0);  CP_COMMIT();                                            \
    LOAD_TILE(1, 32); CP_COMMIT();                                            \
    int T = (K) >> 5;                                                         \
    int stg = 0;                                                              \
    for (int tt = 0; tt < T; tt++) {                                          \
        if (tt == T-1) { CP_WAIT(0); } else { CP_WAIT(1); }                   \
        __syncthreads();                                                      \
        if (tt+2 < T) {                                                       \
            int sn = stg+2; if (sn >= 3) sn -= 3;                             \
            LOAD_TILE(sn, (tt+2)*32);                                         \
            CP_COMMIT();                                                      \
        }                                                                     \
        uint32_t asu = smb + stg*(STG_H*2) + a_off;                           \
        uint32_t bsu = smb + stg*(STG_H*2) + b_off;                           \
        _Pragma("unroll")                                                     \
        for (int kb = 0; kb < 2; kb++) {                                      \
            unsigned af[4][4], bf[8][2];                                      \
            _Pragma("unroll")                                                 \
            for (int mf = 0; mf < 4; mf++)                                    \
                LDSM4(af[mf][0], af[mf][1], af[mf][2], af[mf][3],             \
                      asu + mf*(16*144) + kb*32);                             \
            _Pragma("unroll")                                                 \
            for (int nf2 = 0; nf2 < 4; nf2++)                                 \
                LDSM4(bf[2*nf2][0], bf[2*nf2][1], bf[2*nf2+1][0], bf[2*nf2+1][1], \
                      bsu + nf2*(16*144) + kb*32);                            \
            _Pragma("unroll")                                                 \
            for (int mf = 0; mf < 4; mf++)                                    \
                _Pragma("unroll")                                             \
                for (int nf = 0; nf < 8; nf++)                                \
                    mma_h(acc[mf][nf], af[mf], bf[nf]);                       \
        }                                                                     \
        if (++stg >= 3) stg = 0;                                              \
    }

#define LOAD_TILE(stg, k0) do {                                               \
    __half* sA = smh + (stg)*STG_H;                                           \
    __half* sB = sA + ASTG_H;                                                 \
    _Pragma("unroll")                                                         \
    for (int it = 0; it < 2; it++) {                                          \
        int idx = tid + it*256;                                               \
        int r = idx >> 2, c = idx & 3;                                        \
        cpasync16(&sA[r*72 + c*8], &A[(size_t)(m0+r)*K_ + (k0) + c*8]);       \
    }                                                                         \
    _Pragma("unroll")                                                         \
    for (int it = 0; it < 4; it++) {                                          \
        int idx = tid + it*256;                                               \
        int r = idx >> 2, c = idx & 3;                                        \
        cpasync16(&sB[r*72 + c*8], &Bm[(size_t)(n0+r)*K_ + (k0) + c*8]);      \
    }                                                                         \
} while (0)

// ========== QKV GEMM with fused rotary/transpose epilogue ===================
#define ESTR 264

__global__ __launch_bounds__(256) void gemm_qkv() {
    extern __shared__ __half smh[];
    const __half* A  = g_Xh;
    const __half* Bm = g_Wqkvh;
    const int K_ = DM_;
    int tid = threadIdx.x, wid = tid >> 5, lane = tid & 31;
    int g = lane >> 2, t = lane & 3;
    int wm = (wid & 1)*64, wn = (wid >> 1)*64;
    int m0 = blockIdx.y*128, n0 = blockIdx.x*256;

    GEMM_MAINLOOP(A, Bm, K_)

    // ---- stage fp32 tile to smem ----
    __syncthreads();
    float* Es = (float*)smh;
    #pragma unroll
    for (int mf = 0; mf < 4; mf++) {
        #pragma unroll
        for (int nf = 0; nf < 8; nf++) {
            int row = wm + mf*16 + g;
            int col = wn + nf*8 + 2*t;
            *(float2*)&Es[row*ESTR + col]     = make_float2(acc[mf][nf][0], acc[mf][nf][1]);
            *(float2*)&Es[(row+8)*ESTR + col] = make_float2(acc[mf][nf][2], acc[mf][nf][3]);
        }
    }
    __syncthreads();

    int bb = m0 >> 11;
    int sbase = m0 & (S_-1);

    if (n0 < 2048) {
        const float swq = 0.08838834764831845f * 1.4426950408889634f;
        int d = tid & 63, rh = tid >> 6;
        #pragma unroll 2
        for (int hh = 0; hh < 2; hh++) {
            int h = (n0 >> 7) + hh;
            size_t obase = (size_t)(bb*H_ + h) * S_;
            for (int it = 0; it < 32; it++) {
                int r = rh + it*4;
                float x1 = Es[r*ESTR + hh*128 + d];
                float x2 = Es[r*ESTR + hh*128 + d + 64];
                int s = sbase + r;
                float c = g_qc[s*64+d], sn = g_qs[s*64+d];
                size_t ob = (obase + s)*DH_;
                g_Qh[ob + d]      = __float2half_rn(swq*(x1*c - x2*sn));
                g_Qh[ob + d + 64] = __float2half_rn(swq*(x2*c + x1*sn));
            }
        }
    } else {
        const float sw = 0.08838834764831845f;
        int d = tid & 63, rh = tid >> 6;
        for (int it = 0; it < 32; it++) {
            int r = rh + it*4;
            float x1 = Es[r*ESTR + d];
            float x2 = Es[r*ESTR + d + 64];
            int s = sbase + r;
            float c = g_kc[s*64+d], sn = g_ks[s*64+d];
            size_t ob = ((size_t)(bb*S_ + s))*DH_;
            g_Kh[ob + d]      = __float2half_rn(sw*(x1*c - x2*sn));
            g_Kh[ob + d + 64] = __float2half_rn(sw*(x2*c + x1*sn));
        }
        int r = tid & 127, dh = tid >> 7;
        for (int d2 = 0; d2 < 64; d2++) {
            int d = dh*64 + d2;
            g_Vt[((size_t)(bb*DH_ + d))*S_ + sbase + r] =
                __float2half_rn(Es[r*ESTR + 128 + d]);
        }
    }
}

// ========== proj GEMM: out(f32) = ctx @ Wp^T + bias =========================
__global__ __launch_bounds__(256) void gemm_h(
        const __half* __restrict__ A, const __half* __restrict__ Bm,
        float* __restrict__ C, int M, int N, int K_,
        const float* __restrict__ bias) {
    extern __shared__ __half smh[];
    int tid = threadIdx.x, wid = tid >> 5, lane = tid & 31;
    int g = lane >> 2, t = lane & 3;
    int wm = (wid & 1)*64, wn = (wid >> 1)*64;
    int m0 = blockIdx.y*128, n0 = blockIdx.x*256;

    GEMM_MAINLOOP(A, Bm, K_)

    #pragma unroll
    for (int mf = 0; mf < 4; mf++) {
        #pragma unroll
        for (int nf = 0; nf < 8; nf++) {
            int row = m0 + wm + mf*16 + g;
            int col = n0 + wn + nf*8 + 2*t;
            float b0 = bias[col], b1 = bias[col+1];
            *(float2*)&C[(size_t)row*N + col] =
                make_float2(acc[mf][nf][0]+b0, acc[mf][nf][1]+b1);
            *(float2*)&C[(size_t)(row+8)*N + col] =
                make_float2(acc[mf][nf][2]+b0, acc[mf][nf][3]+b1);
        }
    }
}

// ---------------- flash attention (fp16 mma + ldmatrix) --------------------
#define KS_H (128*136)
#define VS_H (128*136)
#define FSTG_H (KS_H + VS_H)
#define FL_SMEM (2*FSTG_H*2)

__global__ __launch_bounds__(256) void flash_attn() {
    extern __shared__ __half smf[];
    int tid = threadIdx.x;
    int wid = tid >> 5, lane = tid & 31;
    int g = lane >> 2, t = lane & 3;
    int bh = blockIdx.y, b = bh >> 4, h = bh & 15;
    int qt = gridDim.x - 1 - blockIdx.x;   // longest work first
    int q0 = qt * 128;
    int wrow = wid * 16;
    const __half* Qb  = g_Qh + (size_t)bh * S_ * DH_;
    const __half* Kb  = g_Kh + (size_t)b  * S_ * DH_;
    const __half* Vtb = g_Vt + (size_t)b  * DH_ * S_;

    // B-type ldmatrix lane offset (rows = n/d dimension, stride 136 halves)
    uint32_t smfb = smem_u32(smf);
    uint32_t bmap = ((((lane >> 4)<<3) + (lane & 7))*136 + ((lane >> 3)&1)*8)*2;

    unsigned qa[8][4];
    {
        int r0 = q0 + wrow + g;
        #pragma unroll
        for (int kb = 0; kb < 8; kb++) {
            int c0 = kb*16 + 2*t;
            qa[kb][0] = *(const unsigned*)&Qb[(size_t)r0*DH_ + c0];
            qa[kb][1] = *(const unsigned*)&Qb[(size_t)(r0+8)*DH_ + c0];
            qa[kb][2] = *(const unsigned*)&Qb[(size_t)r0*DH_ + c0 + 8];
            qa[kb][3] = *(const unsigned*)&Qb[(size_t)(r0+8)*DH_ + c0 + 8];
        }
    }
    float oacc[16][4];
    #pragma unroll
    for (int i=0;i<16;i++)
        #pragma unroll
        for (int j=0;j<4;j++) oacc[i][j]=0.f;
    float mrow[2] = {-1e30f,-1e30f}, lrow[2] = {0.f,0.f};

    int ntiles = qt + 1;
    #define LOAD_KV(stg, j0) do {                                             \
        __half* Ks_ = smf + (stg)*FSTG_H;                                     \
        __half* Vs_ = Ks_ + KS_H;                                             \
        _Pragma("unroll")                                                     \
        for (int it = 0; it < 8; it++) {                                      \
            int idx = tid + it*256;                                           \
            int r = idx >> 4, c = idx & 15;                                   \
            cpasync16(&Ks_[r*136 + c*8], &Kb[(size_t)((j0)+r)*DH_ + c*8]);    \
        }                                                                     \
        _Pragma("unroll")                                                     \
        for (int it = 0; it < 8; it++) {                                      \
            int idx = tid + it*256;                                           \
            int r = idx >> 4, c = idx & 15;                                   \
            cpasync16(&Vs_[r*136 + c*8], &Vtb[(size_t)r*S_ + (j0) + c*8]);    \
        }                                                                     \
    } while (0)

    LOAD_KV(0, 0);
    CP_COMMIT();

    for (int kt = 0; kt < ntiles; kt++) {
        if (kt+1 < ntiles) {
            LOAD_KV((kt+1)&1, (kt+1)*128);
            CP_COMMIT();
            CP_WAIT(1);
        } else {
            CP_WAIT(0);
        }
        __syncthreads();
        uint32_t ksu = smfb + (kt&1)*(FSTG_H*2) + bmap;
        uint32_t vsu = ksu + KS_H*2;
        int j0 = kt * 128;

        // S = Q @ K^T : warp computes 16x128 (ldmatrix fragments)
        float s[16][4];
        #pragma unroll
        for (int i=0;i<16;i++)
            #pragma unroll
            for (int j=0;j<4;j++) s[i][j]=0.f;
        #pragma unroll
        for (int kb = 0; kb < 8; kb++) {
            #pragma unroll
            for (int nf2 = 0; nf2 < 8; nf2++) {
                unsigned b0,b1,b2,b3;
                LDSM4(b0,b1,b2,b3, ksu + nf2*(16*272) + kb*32);
                unsigned bb0[2] = {b0,b1}, bb1[2] = {b2,b3};
                mma_h(s[2*nf2],   qa[kb], bb0);
                mma_h(s[2*nf2+1], qa[kb], bb1);
            }
        }
        // causal mask (diagonal tile only)
        if (kt == ntiles-1) {
            int r0 = q0 + wrow + g;
            #pragma unroll
            for (int nf = 0; nf < 16; nf++) {
                int c0 = j0 + nf*8 + 2*t;
                if (c0   > r0)   s[nf][0] = -1e30f;
                if (c0+1 > r0)   s[nf][1] = -1e30f;
                if (c0   > r0+8) s[nf][2] = -1e30f;
                if (c0+1 > r0+8) s[nf][3] = -1e30f;
            }
        }
        // online softmax in log2 domain
        #pragma unroll
        for (int rr = 0; rr < 2; rr++) {
            float mx = -1e30f;
            #pragma unroll
            for (int nf = 0; nf < 16; nf++)
                mx = fmaxf(mx, fmaxf(s[nf][2*rr], s[nf][2*rr+1]));
            mx = fmaxf(mx, __shfl_xor_sync(0xffffffffu, mx, 1));
            mx = fmaxf(mx, __shfl_xor_sync(0xffffffffu, mx, 2));
            float mn = fmaxf(mrow[rr], mx);
            float corr = exp2f(mrow[rr] - mn);
            mrow[rr] = mn;
            float rs = 0.f;
            #pragma unroll
            for (int nf = 0; nf < 16; nf++) {
                float e0 = exp2f(s[nf][2*rr]   - mn);
                float e1 = exp2f(s[nf][2*rr+1] - mn);
                s[nf][2*rr] = e0; s[nf][2*rr+1] = e1;
                rs += e0 + e1;
            }
            rs += __shfl_xor_sync(0xffffffffu, rs, 1);
            rs += __shfl_xor_sync(0xffffffffu, rs, 2);
            lrow[rr] = lrow[rr]*corr + rs;
            #pragma unroll
            for (int nf = 0; nf < 16; nf++) {
                oacc[nf][2*rr]   *= corr;
                oacc[nf][2*rr+1] *= corr;
            }
        }
        // O += P @ V  (P in registers; V fragments via ldmatrix)
        #pragma unroll
        for (int kb2 = 0; kb2 < 8; kb2++) {
            unsigned pa[4];
            pa[0] = packh2(s[2*kb2][0],   s[2*kb2][1]);
            pa[1] = packh2(s[2*kb2][2],   s[2*kb2][3]);
            pa[2] = packh2(s[2*kb2+1][0], s[2*kb2+1][1]);
            pa[3] = packh2(s[2*kb2+1][2], s[2*kb2+1][3]);
            #pragma unroll
            for (int nf2 = 0; nf2 < 8; nf2++) {
                unsigned b0,b1,b2,b3;
                LDSM4(b0,b1,b2,b3, vsu + nf2*(16*272) + kb2*32);
                unsigned bb0[2] = {b0,b1}, bb1[2] = {b2,b3};
                mma_h(oacc[2*nf2],   pa, bb0);
                mma_h(oacc[2*nf2+1], pa, bb1);
            }
        }
        __syncthreads();
    }
    #pragma unroll
    for (int rr = 0; rr < 2; rr++) {
        float inv = 1.f / lrow[rr];
        int row = q0 + wrow + g + 8*rr;
        size_t base = ((size_t)(b*S_ + row))*DM_ + h*DH_;
        #pragma unroll
        for (int nf = 0; nf < 16; nf++) {
            __half2 hv = __floats2half2_rn(oacc[nf][2*rr]*inv, oacc[nf][2*rr+1]*inv);
            *(__half2*)&g_ctxh[base + nf*8 + 2*t] = hv;
        }
    }
    #undef LOAD_KV
}

// ---------------- launch ----------------
extern "C" void kernel_launch(void* const* d_in, const int* in_sizes, int n_in,
                              void* d_out, int out_size) {
    const float* X     = (const float*)d_in[0];
    const float* Wq    = (const float*)d_in[1];
    const float* Wkv   = (const float*)d_in[2];
    const float* Wproj = (const float*)d_in[3];
    const float* bproj = (const float*)d_in[4];
    float* out = (float*)d_out;

    static int attr_set = 0;
    if (!attr_set) {
        cudaFuncSetAttribute(flash_attn, cudaFuncAttributeMaxDynamicSharedMemorySize, FL_SMEM);
        cudaFuncSetAttribute(gemm_h,     cudaFuncAttributeMaxDynamicSharedMemorySize, G_SMEM);
        cudaFuncSetAttribute(gemm_qkv,   cudaFuncAttributeMaxDynamicSharedMemorySize, G_SMEM);
        attr_set = 1;
    }

    __half* ctxh; cudaGetSymbolAddress((void**)&ctxh, g_ctxh);
    __half* wph;  cudaGetSymbolAddress((void**)&wph,  g_Wph);

    const int M = B_*S_;   // 4096

    rotary_tables<<<(S_*64+255)/256, 256>>>();
    cvt_all<<<(N4_TOT+1023)/1024, 256>>>((const float4*)X, (const float4*)Wq,
                                         (const float4*)Wkv, (const float4*)Wproj);
    gemm_qkv<<<dim3(NQKV/256, M/128), 256, G_SMEM>>>();
    flash_attn<<<dim3(S_/128, B_*H_), 256, FL_SMEM>>>();
    gemm_h<<<dim3(DM_/256, M/128), 256, G_SMEM>>>(ctxh, wph, out, M, DM_, DM_, bproj);
}

// round 9
// speedup vs baseline: 1.1555x; 1.1285x over previous
#include <cuda_runtime.h>
#include <cuda_fp16.h>
#include <math.h>
#include <stdint.h>

#define B_  2
#define S_  2048
#define DM_ 2048
#define H_  16
#define DH_ 128
#define NQKV 2304   // 2048 q + 128 k + 128 v

// ---------------- scratch (device globals: allocation-free) ----------------
__device__ __half g_Xh[B_*S_*DM_];
__device__ __half g_Wqkvh[NQKV*DM_];       // rows: 0..2047 Wq, 2048..2175 Wk, 2176..2303 Wv
__device__ __half g_Wph[DM_*DM_];
__device__ __half g_Qh[B_*H_*S_*DH_];      // [B,H,S,D]  (scaled by sw*log2e)
__device__ __half g_Kh[B_*S_*DH_];         // [B,S,D]    (scaled by sw)
__device__ __half g_Vt[B_*DH_*S_];         // [B,D,S]
__device__ __half g_ctxh[B_*S_*DM_];
__device__ float  g_qc[S_*64], g_qs[S_*64], g_kc[S_*64], g_ks[S_*64];

// ---------------- helpers ----------------
__device__ __forceinline__ void mma_h(float c[4], const unsigned a[4], const unsigned b[2]) {
    asm volatile(
        "mma.sync.aligned.m16n8k16.row.col.f32.f16.f16.f32 "
        "{%0,%1,%2,%3},{%4,%5,%6,%7},{%8,%9},{%0,%1,%2,%3};"
        : "+f"(c[0]), "+f"(c[1]), "+f"(c[2]), "+f"(c[3])
        : "r"(a[0]), "r"(a[1]), "r"(a[2]), "r"(a[3]), "r"(b[0]), "r"(b[1]));
}
__device__ __forceinline__ void cpasync16(void* s, const void* g) {
    unsigned sa = (unsigned)__cvta_generic_to_shared(s);
    asm volatile("cp.async.cg.shared.global [%0], [%1], 16;" :: "r"(sa), "l"(g));
}
#define CP_COMMIT() asm volatile("cp.async.commit_group;" ::: "memory")
#define CP_WAIT(n)  asm volatile("cp.async.wait_group %0;" :: "n"(n) : "memory")
__device__ __forceinline__ unsigned packh2(float x, float y) {
    __half2 h = __floats2half2_rn(x, y);
    return *(unsigned*)&h;
}
__device__ __forceinline__ uint32_t smem_u32(const void* p) {
    return (uint32_t)__cvta_generic_to_shared(p);
}
#define LDSM4(r0,r1,r2,r3, a)                                                 \
    asm volatile("ldmatrix.sync.aligned.m8n8.x4.shared.b16 {%0,%1,%2,%3}, [%4];" \
        : "=r"(r0), "=r"(r1), "=r"(r2), "=r"(r3) : "r"(a))

// ---------------- prep: fp32->fp16 convert of all tensors + rotary tables --
#define N4_X  (B_*S_*DM_/4)
#define N4_WQ (DM_*DM_/4)
#define N4_WKV (2*DH_*DM_/4)
#define N4_WP (DM_*DM_/4)
#define N4_TOT (N4_X + N4_WQ + N4_WKV + N4_WP)
#define CVT_BLOCKS ((N4_TOT + 1023)/1024)
#define ROT_BLOCKS ((S_*64 + 255)/256)

__global__ void prep_all(const float4* __restrict__ X, const float4* __restrict__ Wq,
                         const float4* __restrict__ Wkv, const float4* __restrict__ Wp) {
    int bid = blockIdx.x;
    if (bid < CVT_BLOCKS) {
        int i = bid*1024 + threadIdx.x;
        #pragma unroll
        for (int k = 0; k < 4; k++) {
            int j = i + k*256;
            if (j >= N4_TOT) return;
            const float4* src; __half2* dst; int off;
            if (j < N4_X) {
                src = X; dst = (__half2*)g_Xh; off = j;
            } else if (j < N4_X + N4_WQ) {
                src = Wq; dst = (__half2*)g_Wqkvh; off = j - N4_X;
            } else if (j < N4_X + N4_WQ + N4_WKV) {
                src = Wkv; dst = (__half2*)(g_Wqkvh + (size_t)DM_*DM_); off = j - N4_X - N4_WQ;
            } else {
                src = Wp; dst = (__half2*)g_Wph; off = j - N4_X - N4_WQ - N4_WKV;
            }
            float4 v = src[off];
            dst[2*off]   = __floats2half2_rn(v.x, v.y);
            dst[2*off+1] = __floats2half2_rn(v.z, v.w);
        }
    } else {
        int idx = (bid - CVT_BLOCKS)*256 + threadIdx.x;
        if (idx >= S_*64) return;
        int s = idx >> 6, j = idx & 63;
        float inv_freq = powf(10000.0f, -(2.0f*j)/128.0f);
        float pos = (float)s * inv_freq;
        float sb = (2.0f*j + 0.4f*128.0f) / (1.4f*128.0f);
        float power = ((float)s - (float)(S_/2)) / 512.0f;
        float xs = powf(sb, power);
        float c = cosf(pos), sn = sinf(pos);
        g_qc[idx] = c*xs;  g_qs[idx] = sn*xs;
        g_kc[idx] = c/xs;  g_ks[idx] = sn/xs;
    }
}

// ========== shared GEMM mainloop macro: CTA 128x256, BK=64, 2-stage =========
// fragment loads via ldmatrix.x4; load issued after sync (prefetch dist = 1 iter)
#define ASTG_H (128*72)
#define BSTG_H (256*72)
#define STG_H  (ASTG_H + BSTG_H)
#define G_SMEM 135168   // epilogue fp32 staging (128*264*4) > mainloop 110592

#define LOAD_TILE(stg, k0) do {                                               \
    __half* sA = smh + (stg)*STG_H;                                           \
    __half* sB = sA + ASTG_H;                                                 \
    _Pragma("unroll")                                                         \
    for (int it = 0; it < 4; it++) {                                          \
        int idx = tid + it*256;                                               \
        int r = idx >> 3, c = idx & 7;                                        \
        cpasync16(&sA[r*72 + c*8], &A[(size_t)(m0+r)*K_ + (k0) + c*8]);       \
    }                                                                         \
    _Pragma("unroll")                                                         \
    for (int it = 0; it < 8; it++) {                                          \
        int idx = tid + it*256;                                               \
        int r = idx >> 3, c = idx & 7;                                        \
        cpasync16(&sB[r*72 + c*8], &Bm[(size_t)(n0+r)*K_ + (k0) + c*8]);      \
    }                                                                         \
} while (0)

#define GEMM_MAINLOOP(A, Bm, K)                                               \
    float acc[4][8][4];                                                       \
    _Pragma("unroll")                                                         \
    for (int i=0;i<4;i++)                                                     \
        _Pragma("unroll")                                                     \
        for (int j=0;j<8;j++)                                                 \
            _Pragma("unroll")                                                 \
            for (int k=0;k<4;k++) acc[i][j][k]=0.f;                           \
    uint32_t smb = smem_u32(smh);                                             \
    uint32_t a_off = ((lane & 15)*72 + (lane >> 4)*8)*2 + wm*144;             \
    uint32_t b_off = ((((lane >> 4)<<3) + (lane & 7))*72 + ((lane >> 3)&1)*8)*2 \
                     + wn*144 + ASTG_H*2;                                     \
    LOAD_TILE(0, 0);  CP_COMMIT();                                            \
    int T = (K) >> 6;                                                         \
    for (int tt = 0; tt < T; tt++) {                                          \
        CP_WAIT(0);                                                           \
        __syncthreads();                                                      \
        if (tt+1 < T) { LOAD_TILE((tt+1)&1, (tt+1)*64); CP_COMMIT(); }        \
        uint32_t asu = smb + (tt&1)*(STG_H*2) + a_off;                        \
        uint32_t bsu = smb + (tt&1)*(STG_H*2) + b_off;                        \
        _Pragma("unroll")                                                     \
        for (int kb = 0; kb < 4; kb++) {                                      \
            unsigned af[4][4], bf[8][2];                                      \
            _Pragma("unroll")                                                 \
            for (int mf = 0; mf < 4; mf++)                                    \
                LDSM4(af[mf][0], af[mf][1], af[mf][2], af[mf][3],             \
                      asu + mf*(16*144) + kb*32);                             \
            _Pragma("unroll")                                                 \
            for (int nf2 = 0; nf2 < 4; nf2++)                                 \
                LDSM4(bf[2*nf2][0], bf[2*nf2][1], bf[2*nf2+1][0], bf[2*nf2+1][1], \
                      bsu + nf2*(16*144) + kb*32);                            \
            _Pragma("unroll")                                                 \
            for (int mf = 0; mf < 4; mf++)                                    \
                _Pragma("unroll")                                             \
                for (int nf = 0; nf < 8; nf++)                                \
                    mma_h(acc[mf][nf], af[mf], bf[nf]);                       \
        }                                                                     \
    }

// ========== QKV GEMM with fused rotary/transpose epilogue ===================
#define ESTR 264

__global__ __launch_bounds__(256) void gemm_qkv() {
    extern __shared__ __half smh[];
    const __half* A  = g_Xh;
    const __half* Bm = g_Wqkvh;
    const int K_ = DM_;
    int tid = threadIdx.x, wid = tid >> 5, lane = tid & 31;
    int g = lane >> 2, t = lane & 3;
    int wm = (wid & 1)*64, wn = (wid >> 1)*64;
    int m0 = blockIdx.y*128, n0 = blockIdx.x*256;

    GEMM_MAINLOOP(A, Bm, K_)

    // ---- stage fp32 tile to smem ----
    __syncthreads();
    float* Es = (float*)smh;
    #pragma unroll
    for (int mf = 0; mf < 4; mf++) {
        #pragma unroll
        for (int nf = 0; nf < 8; nf++) {
            int row = wm + mf*16 + g;
            int col = wn + nf*8 + 2*t;
            *(float2*)&Es[row*ESTR + col]     = make_float2(acc[mf][nf][0], acc[mf][nf][1]);
            *(float2*)&Es[(row+8)*ESTR + col] = make_float2(acc[mf][nf][2], acc[mf][nf][3]);
        }
    }
    __syncthreads();

    int bb = m0 >> 11;
    int sbase = m0 & (S_-1);

    if (n0 < 2048) {
        const float swq = 0.08838834764831845f * 1.4426950408889634f;
        int d = tid & 63, rh = tid >> 6;
        #pragma unroll 2
        for (int hh = 0; hh < 2; hh++) {
            int h = (n0 >> 7) + hh;
            size_t obase = (size_t)(bb*H_ + h) * S_;
            for (int it = 0; it < 32; it++) {
                int r = rh + it*4;
                float x1 = Es[r*ESTR + hh*128 + d];
                float x2 = Es[r*ESTR + hh*128 + d + 64];
                int s = sbase + r;
                float c = g_qc[s*64+d], sn = g_qs[s*64+d];
                size_t ob = (obase + s)*DH_;
                g_Qh[ob + d]      = __float2half_rn(swq*(x1*c - x2*sn));
                g_Qh[ob + d + 64] = __float2half_rn(swq*(x2*c + x1*sn));
            }
        }
    } else {
        const float sw = 0.08838834764831845f;
        int d = tid & 63, rh = tid >> 6;
        for (int it = 0; it < 32; it++) {
            int r = rh + it*4;
            float x1 = Es[r*ESTR + d];
            float x2 = Es[r*ESTR + d + 64];
            int s = sbase + r;
            float c = g_kc[s*64+d], sn = g_ks[s*64+d];
            size_t ob = ((size_t)(bb*S_ + s))*DH_;
            g_Kh[ob + d]      = __float2half_rn(sw*(x1*c - x2*sn));
            g_Kh[ob + d + 64] = __float2half_rn(sw*(x2*c + x1*sn));
        }
        int r = tid & 127, dh = tid >> 7;
        for (int d2 = 0; d2 < 64; d2++) {
            int d = dh*64 + d2;
            g_Vt[((size_t)(bb*DH_ + d))*S_ + sbase + r] =
                __float2half_rn(Es[r*ESTR + 128 + d]);
        }
    }
}

// ========== proj GEMM: out(f32) = ctx @ Wp^T + bias =========================
__global__ __launch_bounds__(256) void gemm_h(
        const __half* __restrict__ A, const __half* __restrict__ Bm,
        float* __restrict__ C, int M, int N, int K_,
        const float* __restrict__ bias) {
    extern __shared__ __half smh[];
    int tid = threadIdx.x, wid = tid >> 5, lane = tid & 31;
    int g = lane >> 2, t = lane & 3;
    int wm = (wid & 1)*64, wn = (wid >> 1)*64;
    int m0 = blockIdx.y*128, n0 = blockIdx.x*256;

    GEMM_MAINLOOP(A, Bm, K_)

    #pragma unroll
    for (int mf = 0; mf < 4; mf++) {
        #pragma unroll
        for (int nf = 0; nf < 8; nf++) {
            int row = m0 + wm + mf*16 + g;
            int col = n0 + wn + nf*8 + 2*t;
            float b0 = bias[col], b1 = bias[col+1];
            *(float2*)&C[(size_t)row*N + col] =
                make_float2(acc[mf][nf][0]+b0, acc[mf][nf][1]+b1);
            *(float2*)&C[(size_t)(row+8)*N + col] =
                make_float2(acc[mf][nf][2]+b0, acc[mf][nf][3]+b1);
        }
    }
}

// ---------------- flash attention (fp16 mma + pipelined ldmatrix) ----------
#define KS_H (128*136)
#define VS_H (128*136)
#define FSTG_H (KS_H + VS_H)
#define FL_SMEM (2*FSTG_H*2)

__global__ __launch_bounds__(256) void flash_attn() {
    extern __shared__ __half smf[];
    int tid = threadIdx.x;
    int wid = tid >> 5, lane = tid & 31;
    int g = lane >> 2, t = lane & 3;
    int bh = blockIdx.y, b = bh >> 4, h = bh & 15;
    int qt = gridDim.x - 1 - blockIdx.x;   // longest work first
    int q0 = qt * 128;
    int wrow = wid * 16;
    const __half* Qb  = g_Qh + (size_t)bh * S_ * DH_;
    const __half* Kb  = g_Kh + (size_t)b  * S_ * DH_;
    const __half* Vtb = g_Vt + (size_t)b  * DH_ * S_;

    uint32_t smfb = smem_u32(smf);
    uint32_t bmap = ((((lane >> 4)<<3) + (lane & 7))*136 + ((lane >> 3)&1)*8)*2;

    unsigned qa[8][4];
    {
        int r0 = q0 + wrow + g;
        #pragma unroll
        for (int kb = 0; kb < 8; kb++) {
            int c0 = kb*16 + 2*t;
            qa[kb][0] = *(const unsigned*)&Qb[(size_t)r0*DH_ + c0];
            qa[kb][1] = *(const unsigned*)&Qb[(size_t)(r0+8)*DH_ + c0];
            qa[kb][2] = *(const unsigned*)&Qb[(size_t)r0*DH_ + c0 + 8];
            qa[kb][3] = *(const unsigned*)&Qb[(size_t)(r0+8)*DH_ + c0 + 8];
        }
    }
    float oacc[16][4];
    #pragma unroll
    for (int i=0;i<16;i++)
        #pragma unroll
        for (int j=0;j<4;j++) oacc[i][j]=0.f;
    float mrow[2] = {-1e30f,-1e30f}, lrow[2] = {0.f,0.f};

    int ntiles = qt + 1;
    #define LOAD_KV(stg, j0) do {                                             \
        __half* Ks_ = smf + (stg)*FSTG_H;                                     \
        __half* Vs_ = Ks_ + KS_H;                                             \
        _Pragma("unroll")                                                     \
        for (int it = 0; it < 8; it++) {                                      \
            int idx = tid + it*256;                                           \
            int r = idx >> 4, c = idx & 15;                                   \
            cpasync16(&Ks_[r*136 + c*8], &Kb[(size_t)((j0)+r)*DH_ + c*8]);    \
        }                                                                     \
        _Pragma("unroll")                                                     \
        for (int it = 0; it < 8; it++) {                                      \
            int idx = tid + it*256;                                           \
            int r = idx >> 4, c = idx & 15;                                   \
            cpasync16(&Vs_[r*136 + c*8], &Vtb[(size_t)r*S_ + (j0) + c*8]);    \
        }                                                                     \
    } while (0)

    LOAD_KV(0, 0);
    CP_COMMIT();

    for (int kt = 0; kt < ntiles; kt++) {
        if (kt+1 < ntiles) {
            LOAD_KV((kt+1)&1, (kt+1)*128);
            CP_COMMIT();
            CP_WAIT(1);
        } else {
            CP_WAIT(0);
        }
        __syncthreads();
        uint32_t ksu = smfb + (kt&1)*(FSTG_H*2) + bmap;
        uint32_t vsu = ksu + KS_H*2;
        int j0 = kt * 128;

        // S = Q @ K^T : software-pipelined LDSM (one always in flight)
        float s[16][4];
        #pragma unroll
        for (int i=0;i<16;i++)
            #pragma unroll
            for (int j=0;j<4;j++) s[i][j]=0.f;
        {
            unsigned pf0,pf1,pf2,pf3;
            LDSM4(pf0,pf1,pf2,pf3, ksu);
            #pragma unroll
            for (int i = 0; i < 64; i++) {
                unsigned c0=pf0, c1=pf1, c2=pf2, c3=pf3;
                if (i < 63) {
                    int j = i + 1;
                    LDSM4(pf0,pf1,pf2,pf3, ksu + (j&7)*(16*272) + (j>>3)*32);
                }
                unsigned bb0[2] = {c0,c1}, bb1[2] = {c2,c3};
                int nf2 = i & 7, kb = i >> 3;
                mma_h(s[2*nf2],   qa[kb], bb0);
                mma_h(s[2*nf2+1], qa[kb], bb1);
            }
        }
        // causal mask (diagonal tile only)
        if (kt == ntiles-1) {
            int r0 = q0 + wrow + g;
            #pragma unroll
            for (int nf = 0; nf < 16; nf++) {
                int c0 = j0 + nf*8 + 2*t;
                if (c0   > r0)   s[nf][0] = -1e30f;
                if (c0+1 > r0)   s[nf][1] = -1e30f;
                if (c0   > r0+8) s[nf][2] = -1e30f;
                if (c0+1 > r0+8) s[nf][3] = -1e30f;
            }
        }
        // online softmax in log2 domain
        #pragma unroll
        for (int rr = 0; rr < 2; rr++) {
            float mx = -1e30f;
            #pragma unroll
            for (int nf = 0; nf < 16; nf++)
                mx = fmaxf(mx, fmaxf(s[nf][2*rr], s[nf][2*rr+1]));
            mx = fmaxf(mx, __shfl_xor_sync(0xffffffffu, mx, 1));
            mx = fmaxf(mx, __shfl_xor_sync(0xffffffffu, mx, 2));
            float mn = fmaxf(mrow[rr], mx);
            float corr = exp2f(mrow[rr] - mn);
            mrow[rr] = mn;
            float rs = 0.f;
            #pragma unroll
            for (int nf = 0; nf < 16; nf++) {
                float e0 = exp2f(s[nf][2*rr]   - mn);
                float e1 = exp2f(s[nf][2*rr+1] - mn);
                s[nf][2*rr] = e0; s[nf][2*rr+1] = e1;
                rs += e0 + e1;
            }
            rs += __shfl_xor_sync(0xffffffffu, rs, 1);
            rs += __shfl_xor_sync(0xffffffffu, rs, 2);
            lrow[rr] = lrow[rr]*corr + rs;
            #pragma unroll
            for (int nf = 0; nf < 16; nf++) {
                oacc[nf][2*rr]   *= corr;
                oacc[nf][2*rr+1] *= corr;
            }
        }
        // O += P @ V  (P in registers; V LDSM pipelined)
        {
            unsigned pf0,pf1,pf2,pf3;
            LDSM4(pf0,pf1,pf2,pf3, vsu);
            unsigned pa[4];
            #pragma unroll
            for (int i = 0; i < 64; i++) {
                int nf2 = i & 7, kb2 = i >> 3;
                if (nf2 == 0) {
                    pa[0] = packh2(s[2*kb2][0],   s[2*kb2][1]);
                    pa[1] = packh2(s[2*kb2][2],   s[2*kb2][3]);
                    pa[2] = packh2(s[2*kb2+1][0], s[2*kb2+1][1]);
                    pa[3] = packh2(s[2*kb2+1][2], s[2*kb2+1][3]);
                }
                unsigned c0=pf0, c1=pf1, c2=pf2, c3=pf3;
                if (i < 63) {
                    int j = i + 1;
                    LDSM4(pf0,pf1,pf2,pf3, vsu + (j&7)*(16*272) + (j>>3)*32);
                }
                unsigned bb0[2] = {c0,c1}, bb1[2] = {c2,c3};
                mma_h(oacc[2*nf2],   pa, bb0);
                mma_h(oacc[2*nf2+1], pa, bb1);
            }
        }
        __syncthreads();
    }
    #pragma unroll
    for (int rr = 0; rr < 2; rr++) {
        float inv = 1.f / lrow[rr];
        int row = q0 + wrow + g + 8*rr;
        size_t base = ((size_t)(b*S_ + row))*DM_ + h*DH_;
        #pragma unroll
        for (int nf = 0; nf < 16; nf++) {
            __half2 hv = __floats2half2_rn(oacc[nf][2*rr]*inv, oacc[nf][2*rr+1]*inv);
            *(__half2*)&g_ctxh[base + nf*8 + 2*t] = hv;
        }
    }
    #undef LOAD_KV
}

// ---------------- launch ----------------
extern "C" void kernel_launch(void* const* d_in, const int* in_sizes, int n_in,
                              void* d_out, int out_size) {
    const float* X     = (const float*)d_in[0];
    const float* Wq    = (const float*)d_in[1];
    const float* Wkv   = (const float*)d_in[2];
    const float* Wproj = (const float*)d_in[3];
    const float* bproj = (const float*)d_in[4];
    float* out = (float*)d_out;

    static int attr_set = 0;
    if (!attr_set) {
        cudaFuncSetAttribute(flash_attn, cudaFuncAttributeMaxDynamicSharedMemorySize, FL_SMEM);
        cudaFuncSetAttribute(gemm_h,     cudaFuncAttributeMaxDynamicSharedMemorySize, G_SMEM);
        cudaFuncSetAttribute(gemm_qkv,   cudaFuncAttributeMaxDynamicSharedMemorySize, G_SMEM);
        attr_set = 1;
    }

    __half* ctxh; cudaGetSymbolAddress((void**)&ctxh, g_ctxh);
    __half* wph;  cudaGetSymbolAddress((void**)&wph,  g_Wph);

    const int M = B_*S_;   // 4096

    prep_all<<<CVT_BLOCKS + ROT_BLOCKS, 256>>>((const float4*)X, (const float4*)Wq,
                                               (const float4*)Wkv, (const float4*)Wproj);
    gemm_qkv<<<dim3(NQKV/256, M/128), 256, G_SMEM>>>();
    flash_attn<<<dim3(S_/128, B_*H_), 256, FL_SMEM>>>();
    gemm_h<<<dim3(DM_/256, M/128), 256, G_SMEM>>>(ctxh, wph, out, M, DM_, DM_, bproj);
}

// round 10
// speedup vs baseline: 1.2273x; 1.0622x over previous
#include <cuda_runtime.h>
#include <cuda_fp16.h>
#include <math.h>
#include <stdint.h>

#define B_  2
#define S_  2048
#define DM_ 2048
#define H_  16
#define DH_ 128
#define NQKV 2304   // 2048 q + 128 k + 128 v

// ---------------- scratch (device globals: allocation-free) ----------------
__device__ __half g_Xh[B_*S_*DM_];
__device__ __half g_Wqkvh[NQKV*DM_];       // rows: 0..2047 Wq, 2048..2175 Wk, 2176..2303 Wv
__device__ __half g_Wph[DM_*DM_];
__device__ __half g_Qh[B_*H_*S_*DH_];      // [B,H,S,D]  (scaled by sw*log2e)
__device__ __half g_Kh[B_*S_*DH_];         // [B,S,D]    (scaled by sw)
__device__ __half g_Vt[B_*DH_*S_];         // [B,D,S]
__device__ __half g_ctxh[B_*S_*DM_];
__device__ float  g_qc[S_*64], g_qs[S_*64], g_kc[S_*64], g_ks[S_*64];

// ---------------- helpers ----------------
__device__ __forceinline__ void mma_h(float c[4], const unsigned a[4], const unsigned b[2]) {
    asm volatile(
        "mma.sync.aligned.m16n8k16.row.col.f32.f16.f16.f32 "
        "{%0,%1,%2,%3},{%4,%5,%6,%7},{%8,%9},{%0,%1,%2,%3};"
        : "+f"(c[0]), "+f"(c[1]), "+f"(c[2]), "+f"(c[3])
        : "r"(a[0]), "r"(a[1]), "r"(a[2]), "r"(a[3]), "r"(b[0]), "r"(b[1]));
}
__device__ __forceinline__ void cpasync16(void* s, const void* g) {
    unsigned sa = (unsigned)__cvta_generic_to_shared(s);
    asm volatile("cp.async.cg.shared.global [%0], [%1], 16;" :: "r"(sa), "l"(g));
}
#define CP_COMMIT() asm volatile("cp.async.commit_group;" ::: "memory")
#define CP_WAIT(n)  asm volatile("cp.async.wait_group %0;" :: "n"(n) : "memory")
__device__ __forceinline__ unsigned packh2(float x, float y) {
    __half2 h = __floats2half2_rn(x, y);
    return *(unsigned*)&h;
}
__device__ __forceinline__ uint32_t smem_u32(const void* p) {
    return (uint32_t)__cvta_generic_to_shared(p);
}
#define LDSM4(r0,r1,r2,r3, a)                                                 \
    asm volatile("ldmatrix.sync.aligned.m8n8.x4.shared.b16 {%0,%1,%2,%3}, [%4];" \
        : "=r"(r0), "=r"(r1), "=r"(r2), "=r"(r3) : "r"(a))

// ---------------- prep: fp32->fp16 convert of all tensors + rotary tables --
#define N4_X  (B_*S_*DM_/4)
#define N4_WQ (DM_*DM_/4)
#define N4_WKV (2*DH_*DM_/4)
#define N4_WP (DM_*DM_/4)
#define N4_TOT (N4_X + N4_WQ + N4_WKV + N4_WP)
#define CVT_BLOCKS ((N4_TOT + 1023)/1024)
#define ROT_BLOCKS ((S_*64 + 255)/256)

__global__ void prep_all(const float4* __restrict__ X, const float4* __restrict__ Wq,
                         const float4* __restrict__ Wkv, const float4* __restrict__ Wp) {
    int bid = blockIdx.x;
    if (bid < CVT_BLOCKS) {
        int i = bid*1024 + threadIdx.x;
        #pragma unroll
        for (int k = 0; k < 4; k++) {
            int j = i + k*256;
            if (j >= N4_TOT) return;
            const float4* src; __half2* dst; int off;
            if (j < N4_X) {
                src = X; dst = (__half2*)g_Xh; off = j;
            } else if (j < N4_X + N4_WQ) {
                src = Wq; dst = (__half2*)g_Wqkvh; off = j - N4_X;
            } else if (j < N4_X + N4_WQ + N4_WKV) {
                src = Wkv; dst = (__half2*)(g_Wqkvh + (size_t)DM_*DM_); off = j - N4_X - N4_WQ;
            } else {
                src = Wp; dst = (__half2*)g_Wph; off = j - N4_X - N4_WQ - N4_WKV;
            }
            float4 v = src[off];
            dst[2*off]   = __floats2half2_rn(v.x, v.y);
            dst[2*off+1] = __floats2half2_rn(v.z, v.w);
        }
    } else {
        int idx = (bid - CVT_BLOCKS)*256 + threadIdx.x;
        if (idx >= S_*64) return;
        int s = idx >> 6, j = idx & 63;
        float inv_freq = powf(10000.0f, -(2.0f*j)/128.0f);
        float pos = (float)s * inv_freq;
        float sb = (2.0f*j + 0.4f*128.0f) / (1.4f*128.0f);
        float power = ((float)s - (float)(S_/2)) / 512.0f;
        float xs = powf(sb, power);
        float c = cosf(pos), sn = sinf(pos);
        g_qc[idx] = c*xs;  g_qs[idx] = sn*xs;
        g_kc[idx] = c/xs;  g_ks[idx] = sn/xs;
    }
}

// ========== GEMM: CTA 128x256, BK=64, 2-stage, 512 thr (16 warps, 4m x 4n) ==
// warp tile 32x64; fragment loads via ldmatrix.x4
#define ASTG_H (128*72)
#define BSTG_H (256*72)
#define STG_H  (ASTG_H + BSTG_H)
#define G_SMEM 135168   // epilogue fp32 staging (128*264*4) > mainloop 110592

#define LOAD_TILE(stg, k0) do {                                               \
    __half* sA = smh + (stg)*STG_H;                                           \
    __half* sB = sA + ASTG_H;                                                 \
    _Pragma("unroll")                                                         \
    for (int it = 0; it < 2; it++) {                                          \
        int idx = tid + it*512;                                               \
        int r = idx >> 3, c = idx & 7;                                        \
        cpasync16(&sA[r*72 + c*8], &A[(size_t)(m0+r)*K_ + (k0) + c*8]);       \
    }                                                                         \
    _Pragma("unroll")                                                         \
    for (int it = 0; it < 4; it++) {                                          \
        int idx = tid + it*512;                                               \
        int r = idx >> 3, c = idx & 7;                                        \
        cpasync16(&sB[r*72 + c*8], &Bm[(size_t)(n0+r)*K_ + (k0) + c*8]);      \
    }                                                                         \
} while (0)

#define GEMM_MAINLOOP(A, Bm, K)                                               \
    float acc[2][8][4];                                                       \
    _Pragma("unroll")                                                         \
    for (int i=0;i<2;i++)                                                     \
        _Pragma("unroll")                                                     \
        for (int j=0;j<8;j++)                                                 \
            _Pragma("unroll")                                                 \
            for (int k=0;k<4;k++) acc[i][j][k]=0.f;                           \
    uint32_t smb = smem_u32(smh);                                             \
    uint32_t a_off = ((lane & 15)*72 + (lane >> 4)*8)*2 + wm*144;             \
    uint32_t b_off = ((((lane >> 4)<<3) + (lane & 7))*72 + ((lane >> 3)&1)*8)*2 \
                     + wn*144 + ASTG_H*2;                                     \
    LOAD_TILE(0, 0);  CP_COMMIT();                                            \
    int T = (K) >> 6;                                                         \
    for (int tt = 0; tt < T; tt++) {                                          \
        CP_WAIT(0);                                                           \
        __syncthreads();                                                      \
        if (tt+1 < T) { LOAD_TILE((tt+1)&1, (tt+1)*64); CP_COMMIT(); }        \
        uint32_t asu = smb + (tt&1)*(STG_H*2) + a_off;                        \
        uint32_t bsu = smb + (tt&1)*(STG_H*2) + b_off;                        \
        _Pragma("unroll")                                                     \
        for (int kb = 0; kb < 4; kb++) {                                      \
            unsigned af[2][4], bf[8][2];                                      \
            _Pragma("unroll")                                                 \
            for (int mf = 0; mf < 2; mf++)                                    \
                LDSM4(af[mf][0], af[mf][1], af[mf][2], af[mf][3],             \
                      asu + mf*(16*144) + kb*32);                             \
            _Pragma("unroll")                                                 \
            for (int nf2 = 0; nf2 < 4; nf2++)                                 \
                LDSM4(bf[2*nf2][0], bf[2*nf2][1], bf[2*nf2+1][0], bf[2*nf2+1][1], \
                      bsu + nf2*(16*144) + kb*32);                            \
            _Pragma("unroll")                                                 \
            for (int mf = 0; mf < 2; mf++)                                    \
                _Pragma("unroll")                                             \
                for (int nf = 0; nf < 8; nf++)                                \
                    mma_h(acc[mf][nf], af[mf], bf[nf]);                       \
        }                                                                     \
    }

// ========== QKV GEMM with fused rotary/transpose epilogue ===================
#define ESTR 264

__global__ __launch_bounds__(512) void gemm_qkv() {
    extern __shared__ __half smh[];
    const __half* A  = g_Xh;
    const __half* Bm = g_Wqkvh;
    const int K_ = DM_;
    int tid = threadIdx.x, wid = tid >> 5, lane = tid & 31;
    int g = lane >> 2, t = lane & 3;
    int wm = (wid & 3)*32, wn = (wid >> 2)*64;
    int m0 = blockIdx.y*128, n0 = blockIdx.x*256;

    GEMM_MAINLOOP(A, Bm, K_)

    // ---- stage fp32 tile to smem ----
    __syncthreads();
    float* Es = (float*)smh;
    #pragma unroll
    for (int mf = 0; mf < 2; mf++) {
        #pragma unroll
        for (int nf = 0; nf < 8; nf++) {
            int row = wm + mf*16 + g;
            int col = wn + nf*8 + 2*t;
            *(float2*)&Es[row*ESTR + col]     = make_float2(acc[mf][nf][0], acc[mf][nf][1]);
            *(float2*)&Es[(row+8)*ESTR + col] = make_float2(acc[mf][nf][2], acc[mf][nf][3]);
        }
    }
    __syncthreads();

    int bb = m0 >> 11;
    int sbase = m0 & (S_-1);

    if (n0 < 2048) {
        const float swq = 0.08838834764831845f * 1.4426950408889634f;
        int d = tid & 63, rh = tid >> 6;        // rh 0..7
        #pragma unroll 2
        for (int hh = 0; hh < 2; hh++) {
            int h = (n0 >> 7) + hh;
            size_t obase = (size_t)(bb*H_ + h) * S_;
            for (int it = 0; it < 16; it++) {
                int r = rh + it*8;
                float x1 = Es[r*ESTR + hh*128 + d];
                float x2 = Es[r*ESTR + hh*128 + d + 64];
                int s = sbase + r;
                float c = g_qc[s*64+d], sn = g_qs[s*64+d];
                size_t ob = (obase + s)*DH_;
                g_Qh[ob + d]      = __float2half_rn(swq*(x1*c - x2*sn));
                g_Qh[ob + d + 64] = __float2half_rn(swq*(x2*c + x1*sn));
            }
        }
    } else {
        const float sw = 0.08838834764831845f;
        int d = tid & 63, rh = tid >> 6;
        for (int it = 0; it < 16; it++) {
            int r = rh + it*8;
            float x1 = Es[r*ESTR + d];
            float x2 = Es[r*ESTR + d + 64];
            int s = sbase + r;
            float c = g_kc[s*64+d], sn = g_ks[s*64+d];
            size_t ob = ((size_t)(bb*S_ + s))*DH_;
            g_Kh[ob + d]      = __float2half_rn(sw*(x1*c - x2*sn));
            g_Kh[ob + d + 64] = __float2half_rn(sw*(x2*c + x1*sn));
        }
        int r = tid & 127, dh = tid >> 7;       // dh 0..3
        for (int d2 = 0; d2 < 32; d2++) {
            int d = dh*32 + d2;
            g_Vt[((size_t)(bb*DH_ + d))*S_ + sbase + r] =
                __float2half_rn(Es[r*ESTR + 128 + d]);
        }
    }
}

// ========== proj GEMM: out(f32) = ctx @ Wp^T + bias =========================
__global__ __launch_bounds__(512) void gemm_h(
        const __half* __restrict__ A, const __half* __restrict__ Bm,
        float* __restrict__ C, int M, int N, int K_,
        const float* __restrict__ bias) {
    extern __shared__ __half smh[];
    int tid = threadIdx.x, wid = tid >> 5, lane = tid & 31;
    int g = lane >> 2, t = lane & 3;
    int wm = (wid & 3)*32, wn = (wid >> 2)*64;
    int m0 = blockIdx.y*128, n0 = blockIdx.x*256;

    GEMM_MAINLOOP(A, Bm, K_)

    #pragma unroll
    for (int mf = 0; mf < 2; mf++) {
        #pragma unroll
        for (int nf = 0; nf < 8; nf++) {
            int row = m0 + wm + mf*16 + g;
            int col = n0 + wn + nf*8 + 2*t;
            float b0 = bias[col], b1 = bias[col+1];
            *(float2*)&C[(size_t)row*N + col] =
                make_float2(acc[mf][nf][0]+b0, acc[mf][nf][1]+b1);
            *(float2*)&C[(size_t)(row+8)*N + col] =
                make_float2(acc[mf][nf][2]+b0, acc[mf][nf][3]+b1);
        }
    }
}

// ---------------- flash attention (fp16 mma + pipelined ldmatrix) ----------
#define KS_H (128*136)
#define VS_H (128*136)
#define FSTG_H (KS_H + VS_H)
#define FL_SMEM (2*FSTG_H*2)

__global__ __launch_bounds__(256) void flash_attn() {
    extern __shared__ __half smf[];
    int tid = threadIdx.x;
    int wid = tid >> 5, lane = tid & 31;
    int g = lane >> 2, t = lane & 3;
    int bh = blockIdx.y, b = bh >> 4, h = bh & 15;
    int qt = gridDim.x - 1 - blockIdx.x;   // longest work first
    int q0 = qt * 128;
    int wrow = wid * 16;
    const __half* Qb  = g_Qh + (size_t)bh * S_ * DH_;
    const __half* Kb  = g_Kh + (size_t)b  * S_ * DH_;
    const __half* Vtb = g_Vt + (size_t)b  * DH_ * S_;

    uint32_t smfb = smem_u32(smf);
    uint32_t bmap = ((((lane >> 4)<<3) + (lane & 7))*136 + ((lane >> 3)&1)*8)*2;

    unsigned qa[8][4];
    {
        int r0 = q0 + wrow + g;
        #pragma unroll
        for (int kb = 0; kb < 8; kb++) {
            int c0 = kb*16 + 2*t;
            qa[kb][0] = *(const unsigned*)&Qb[(size_t)r0*DH_ + c0];
            qa[kb][1] = *(const unsigned*)&Qb[(size_t)(r0+8)*DH_ + c0];
            qa[kb][2] = *(const unsigned*)&Qb[(size_t)r0*DH_ + c0 + 8];
            qa[kb][3] = *(const unsigned*)&Qb[(size_t)(r0+8)*DH_ + c0 + 8];
        }
    }
    float oacc[16][4];
    #pragma unroll
    for (int i=0;i<16;i++)
        #pragma unroll
        for (int j=0;j<4;j++) oacc[i][j]=0.f;
    float mrow[2] = {-1e30f,-1e30f}, lrow[2] = {0.f,0.f};

    int ntiles = qt + 1;
    #define LOAD_KV(stg, j0) do {                                             \
        __half* Ks_ = smf + (stg)*FSTG_H;                                     \
        __half* Vs_ = Ks_ + KS_H;                                             \
        _Pragma("unroll")                                                     \
        for (int it = 0; it < 8; it++) {                                      \
            int idx = tid + it*256;                                           \
            int r = idx >> 4, c = idx & 15;                                   \
            cpasync16(&Ks_[r*136 + c*8], &Kb[(size_t)((j0)+r)*DH_ + c*8]);    \
        }                                                                     \
        _Pragma("unroll")                                                     \
        for (int it = 0; it < 8; it++) {                                      \
            int idx = tid + it*256;                                           \
            int r = idx >> 4, c = idx & 15;                                   \
            cpasync16(&Vs_[r*136 + c*8], &Vtb[(size_t)r*S_ + (j0) + c*8]);    \
        }                                                                     \
    } while (0)

    LOAD_KV(0, 0);
    CP_COMMIT();

    for (int kt = 0; kt < ntiles; kt++) {
        if (kt+1 < ntiles) {
            LOAD_KV((kt+1)&1, (kt+1)*128);
            CP_COMMIT();
            CP_WAIT(1);
        } else {
            CP_WAIT(0);
        }
        __syncthreads();
        uint32_t ksu = smfb + (kt&1)*(FSTG_H*2) + bmap;
        uint32_t vsu = ksu + KS_H*2;
        int j0 = kt * 128;

        // S = Q @ K^T : software-pipelined LDSM (one always in flight)
        float s[16][4];
        #pragma unroll
        for (int i=0;i<16;i++)
            #pragma unroll
            for (int j=0;j<4;j++) s[i][j]=0.f;
        {
            unsigned pf0,pf1,pf2,pf3;
            LDSM4(pf0,pf1,pf2,pf3, ksu);
            #pragma unroll
            for (int i = 0; i < 64; i++) {
                unsigned c0=pf0, c1=pf1, c2=pf2, c3=pf3;
                if (i < 63) {
                    int j = i + 1;
                    LDSM4(pf0,pf1,pf2,pf3, ksu + (j&7)*(16*272) + (j>>3)*32);
                }
                unsigned bb0[2] = {c0,c1}, bb1[2] = {c2,c3};
                int nf2 = i & 7, kb = i >> 3;
                mma_h(s[2*nf2],   qa[kb], bb0);
                mma_h(s[2*nf2+1], qa[kb], bb1);
            }
        }
        // causal mask (diagonal tile only)
        if (kt == ntiles-1) {
            int r0 = q0 + wrow + g;
            #pragma unroll
            for (int nf = 0; nf < 16; nf++) {
                int c0 = j0 + nf*8 + 2*t;
                if (c0   > r0)   s[nf][0] = -1e30f;
                if (c0+1 > r0)   s[nf][1] = -1e30f;
                if (c0   > r0+8) s[nf][2] = -1e30f;
                if (c0+1 > r0+8) s[nf][3] = -1e30f;
            }
        }
        // online softmax in log2 domain
        #pragma unroll
        for (int rr = 0; rr < 2; rr++) {
            float mx = -1e30f;
            #pragma unroll
            for (int nf = 0; nf < 16; nf++)
                mx = fmaxf(mx, fmaxf(s[nf][2*rr], s[nf][2*rr+1]));
            mx = fmaxf(mx, __shfl_xor_sync(0xffffffffu, mx, 1));
            mx = fmaxf(mx, __shfl_xor_sync(0xffffffffu, mx, 2));
            float mn = fmaxf(mrow[rr], mx);
            float corr = exp2f(mrow[rr] - mn);
            mrow[rr] = mn;
            float rs = 0.f;
            #pragma unroll
            for (int nf = 0; nf < 16; nf++) {
                float e0 = exp2f(s[nf][2*rr]   - mn);
                float e1 = exp2f(s[nf][2*rr+1] - mn);
                s[nf][2*rr] = e0; s[nf][2*rr+1] = e1;
                rs += e0 + e1;
            }
            rs += __shfl_xor_sync(0xffffffffu, rs, 1);
            rs += __shfl_xor_sync(0xffffffffu, rs, 2);
            lrow[rr] = lrow[rr]*corr + rs;
            #pragma unroll
            for (int nf = 0; nf < 16; nf++) {
                oacc[nf][2*rr]   *= corr;
                oacc[nf][2*rr+1] *= corr;
            }
        }
        // O += P @ V  (P in registers; V LDSM pipelined)
        {
            unsigned pf0,pf1,pf2,pf3;
            LDSM4(pf0,pf1,pf2,pf3, vsu);
            unsigned pa[4];
            #pragma unroll
            for (int i = 0; i < 64; i++) {
                int nf2 = i & 7, kb2 = i >> 3;
                if (nf2 == 0) {
                    pa[0] = packh2(s[2*kb2][0],   s[2*kb2][1]);
                    pa[1] = packh2(s[2*kb2][2],   s[2*kb2][3]);
                    pa[2] = packh2(s[2*kb2+1][0], s[2*kb2+1][1]);
                    pa[3] = packh2(s[2*kb2+1][2], s[2*kb2+1][3]);
                }
                unsigned c0=pf0, c1=pf1, c2=pf2, c3=pf3;
                if (i < 63) {
                    int j = i + 1;
                    LDSM4(pf0,pf1,pf2,pf3, vsu + (j&7)*(16*272) + (j>>3)*32);
                }
                unsigned bb0[2] = {c0,c1}, bb1[2] = {c2,c3};
                mma_h(oacc[2*nf2],   pa, bb0);
                mma_h(oacc[2*nf2+1], pa, bb1);
            }
        }
        __syncthreads();
    }
    #pragma unroll
    for (int rr = 0; rr < 2; rr++) {
        float inv = 1.f / lrow[rr];
        int row = q0 + wrow + g + 8*rr;
        size_t base = ((size_t)(b*S_ + row))*DM_ + h*DH_;
        #pragma unroll
        for (int nf = 0; nf < 16; nf++) {
            __half2 hv = __floats2half2_rn(oacc[nf][2*rr]*inv, oacc[nf][2*rr+1]*inv);
            *(__half2*)&g_ctxh[base + nf*8 + 2*t] = hv;
        }
    }
    #undef LOAD_KV
}

// ---------------- launch ----------------
extern "C" void kernel_launch(void* const* d_in, const int* in_sizes, int n_in,
                              void* d_out, int out_size) {
    const float* X     = (const float*)d_in[0];
    const float* Wq    = (const float*)d_in[1];
    const float* Wkv   = (const float*)d_in[2];
    const float* Wproj = (const float*)d_in[3];
    const float* bproj = (const float*)d_in[4];
    float* out = (float*)d_out;

    static int attr_set = 0;
    if (!attr_set) {
        cudaFuncSetAttribute(flash_attn, cudaFuncAttributeMaxDynamicSharedMemorySize, FL_SMEM);
        cudaFuncSetAttribute(gemm_h,     cudaFuncAttributeMaxDynamicSharedMemorySize, G_SMEM);
        cudaFuncSetAttribute(gemm_qkv,   cudaFuncAttributeMaxDynamicSharedMemorySize, G_SMEM);
        attr_set = 1;
    }

    __half* ctxh; cudaGetSymbolAddress((void**)&ctxh, g_ctxh);
    __half* wph;  cudaGetSymbolAddress((void**)&wph,  g_Wph);

    const int M = B_*S_;   // 4096

    prep_all<<<CVT_BLOCKS + ROT_BLOCKS, 256>>>((const float4*)X, (const float4*)Wq,
                                               (const float4*)Wkv, (const float4*)Wproj);
    gemm_qkv<<<dim3(NQKV/256, M/128), 512, G_SMEM>>>();
    flash_attn<<<dim3(S_/128, B_*H_), 256, FL_SMEM>>>();
    gemm_h<<<dim3(DM_/256, M/128), 512, G_SMEM>>>(ctxh, wph, out, M, DM_, DM_, bproj);
}

// round 11
// speedup vs baseline: 1.2522x; 1.0203x over previous
#include <cuda_runtime.h>
#include <cuda_fp16.h>
#include <math.h>
#include <stdint.h>

#define B_  2
#define S_  2048
#define DM_ 2048
#define H_  16
#define DH_ 128
#define NQKV 2304   // 2048 q + 128 k + 128 v

// ---------------- scratch (device globals: allocation-free) ----------------
__device__ __half g_Xh[B_*S_*DM_];
__device__ __half g_Wqkvh[NQKV*DM_];       // rows: 0..2047 Wq, 2048..2175 Wk, 2176..2303 Wv
__device__ __half g_Wph[DM_*DM_];
__device__ __half g_Qh[B_*H_*S_*DH_];      // [B,H,S,D]  (scaled by sw*log2e)
__device__ __half g_Kh[B_*S_*DH_];         // [B,S,D]    (scaled by sw)
__device__ __half g_Vt[B_*DH_*S_];         // [B,D,S]
__device__ __half g_ctxh[B_*S_*DM_];
__device__ float  g_qc[S_*64], g_qs[S_*64], g_kc[S_*64], g_ks[S_*64];

// ---------------- helpers ----------------
__device__ __forceinline__ void mma_h(float c[4], const unsigned a[4], const unsigned b[2]) {
    asm volatile(
        "mma.sync.aligned.m16n8k16.row.col.f32.f16.f16.f32 "
        "{%0,%1,%2,%3},{%4,%5,%6,%7},{%8,%9},{%0,%1,%2,%3};"
        : "+f"(c[0]), "+f"(c[1]), "+f"(c[2]), "+f"(c[3])
        : "r"(a[0]), "r"(a[1]), "r"(a[2]), "r"(a[3]), "r"(b[0]), "r"(b[1]));
}
__device__ __forceinline__ void cpasync16(void* s, const void* g) {
    unsigned sa = (unsigned)__cvta_generic_to_shared(s);
    asm volatile("cp.async.cg.shared.global [%0], [%1], 16;" :: "r"(sa), "l"(g));
}
#define CP_COMMIT() asm volatile("cp.async.commit_group;" ::: "memory")
#define CP_WAIT(n)  asm volatile("cp.async.wait_group %0;" :: "n"(n) : "memory")
__device__ __forceinline__ uint32_t smem_u32(const void* p) {
    return (uint32_t)__cvta_generic_to_shared(p);
}
// pack two f32 to f16x2 (lo = second src) then 2^x on both halves
__device__ __forceinline__ unsigned cvt_h2(float hi, float lo) {
    unsigned r; asm("cvt.rn.f16x2.f32 %0, %1, %2;" : "=r"(r) : "f"(hi), "f"(lo)); return r;
}
__device__ __forceinline__ unsigned ex2_h2(unsigned x) {
    unsigned r; asm("ex2.approx.f16x2 %0, %1;" : "=r"(r) : "r"(x)); return r;
}
#define LDSM4(r0,r1,r2,r3, a)                                                 \
    asm volatile("ldmatrix.sync.aligned.m8n8.x4.shared.b16 {%0,%1,%2,%3}, [%4];" \
        : "=r"(r0), "=r"(r1), "=r"(r2), "=r"(r3) : "r"(a))

// ---------------- prep: fp32->fp16 convert of all tensors + rotary tables --
#define N4_X  (B_*S_*DM_/4)
#define N4_WQ (DM_*DM_/4)
#define N4_WKV (2*DH_*DM_/4)
#define N4_WP (DM_*DM_/4)
#define N4_TOT (N4_X + N4_WQ + N4_WKV + N4_WP)
#define CVT_BLOCKS ((N4_TOT + 1023)/1024)
#define ROT_BLOCKS ((S_*64 + 255)/256)

__global__ void prep_all(const float4* __restrict__ X, const float4* __restrict__ Wq,
                         const float4* __restrict__ Wkv, const float4* __restrict__ Wp) {
    int bid = blockIdx.x;
    if (bid < CVT_BLOCKS) {
        int i = bid*1024 + threadIdx.x;
        #pragma unroll
        for (int k = 0; k < 4; k++) {
            int j = i + k*256;
            if (j >= N4_TOT) return;
            const float4* src; __half2* dst; int off;
            if (j < N4_X) {
                src = X; dst = (__half2*)g_Xh; off = j;
            } else if (j < N4_X + N4_WQ) {
                src = Wq; dst = (__half2*)g_Wqkvh; off = j - N4_X;
            } else if (j < N4_X + N4_WQ + N4_WKV) {
                src = Wkv; dst = (__half2*)(g_Wqkvh + (size_t)DM_*DM_); off = j - N4_X - N4_WQ;
            } else {
                src = Wp; dst = (__half2*)g_Wph; off = j - N4_X - N4_WQ - N4_WKV;
            }
            float4 v = src[off];
            dst[2*off]   = __floats2half2_rn(v.x, v.y);
            dst[2*off+1] = __floats2half2_rn(v.z, v.w);
        }
    } else {
        int idx = (bid - CVT_BLOCKS)*256 + threadIdx.x;
        if (idx >= S_*64) return;
        int s = idx >> 6, j = idx & 63;
        float inv_freq = powf(10000.0f, -(2.0f*j)/128.0f);
        float pos = (float)s * inv_freq;
        float sb = (2.0f*j + 0.4f*128.0f) / (1.4f*128.0f);
        float power = ((float)s - (float)(S_/2)) / 512.0f;
        float xs = powf(sb, power);
        float c = cosf(pos), sn = sinf(pos);
        g_qc[idx] = c*xs;  g_qs[idx] = sn*xs;
        g_kc[idx] = c/xs;  g_ks[idx] = sn/xs;
    }
}

// ========== GEMM: CTA 128x128, BK=64, 2-stage, 256 thr (8 warps 4m x 2n) ====
// warp tile 32x64; fragment loads via ldmatrix.x4; 2 CTAs/SM
#define ASTG_H (128*72)
#define BSTG_H (128*72)
#define STG_H  (ASTG_H + BSTG_H)
#define G_SMEM (2*STG_H*2)   // 73728 B; epilogue staging 128*136*4=69632 fits

#define LOAD_TILE(stg, k0) do {                                               \
    __half* sA = smh + (stg)*STG_H;                                           \
    __half* sB = sA + ASTG_H;                                                 \
    _Pragma("unroll")                                                         \
    for (int it = 0; it < 4; it++) {                                          \
        int idx = tid + it*256;                                               \
        int r = idx >> 3, c = idx & 7;                                        \
        cpasync16(&sA[r*72 + c*8], &A[(size_t)(m0+r)*K_ + (k0) + c*8]);       \
    }                                                                         \
    _Pragma("unroll")                                                         \
    for (int it = 0; it < 4; it++) {                                          \
        int idx = tid + it*256;                                               \
        int r = idx >> 3, c = idx & 7;                                        \
        cpasync16(&sB[r*72 + c*8], &Bm[(size_t)(n0+r)*K_ + (k0) + c*8]);      \
    }                                                                         \
} while (0)

#define GEMM_MAINLOOP(A, Bm, K)                                               \
    float acc[2][8][4];                                                       \
    _Pragma("unroll")                                                         \
    for (int i=0;i<2;i++)                                                     \
        _Pragma("unroll")                                                     \
        for (int j=0;j<8;j++)                                                 \
            _Pragma("unroll")                                                 \
            for (int k=0;k<4;k++) acc[i][j][k]=0.f;                           \
    uint32_t smb = smem_u32(smh);                                             \
    uint32_t a_off = ((lane & 15)*72 + (lane >> 4)*8)*2 + wm*144;             \
    uint32_t b_off = ((((lane >> 4)<<3) + (lane & 7))*72 + ((lane >> 3)&1)*8)*2 \
                     + wn*144 + ASTG_H*2;                                     \
    LOAD_TILE(0, 0);  CP_COMMIT();                                            \
    int T = (K) >> 6;                                                         \
    for (int tt = 0; tt < T; tt++) {                                          \
        CP_WAIT(0);                                                           \
        __syncthreads();                                                      \
        if (tt+1 < T) { LOAD_TILE((tt+1)&1, (tt+1)*64); CP_COMMIT(); }        \
        uint32_t asu = smb + (tt&1)*(STG_H*2) + a_off;                        \
        uint32_t bsu = smb + (tt&1)*(STG_H*2) + b_off;                        \
        _Pragma("unroll")                                                     \
        for (int kb = 0; kb < 4; kb++) {                                      \
            unsigned af[2][4], bf[8][2];                                      \
            _Pragma("unroll")                                                 \
            for (int mf = 0; mf < 2; mf++)                                    \
                LDSM4(af[mf][0], af[mf][1], af[mf][2], af[mf][3],             \
                      asu + mf*(16*144) + kb*32);                             \
            _Pragma("unroll")                                                 \
            for (int nf2 = 0; nf2 < 4; nf2++)                                 \
                LDSM4(bf[2*nf2][0], bf[2*nf2][1], bf[2*nf2+1][0], bf[2*nf2+1][1], \
                      bsu + nf2*(16*144) + kb*32);                            \
            _Pragma("unroll")                                                 \
            for (int mf = 0; mf < 2; mf++)                                    \
                _Pragma("unroll")                                             \
                for (int nf = 0; nf < 8; nf++)                                \
                    mma_h(acc[mf][nf], af[mf], bf[nf]);                       \
        }                                                                     \
    }

// ========== QKV GEMM with fused rotary/transpose epilogue ===================
// grid (18, 32): bx 0..15 -> Q heads (1 head / tile), bx 16 -> K, bx 17 -> V
#define ESTR 136

__global__ __launch_bounds__(256, 2) void gemm_qkv() {
    extern __shared__ __half smh[];
    const __half* A  = g_Xh;
    const __half* Bm = g_Wqkvh;
    const int K_ = DM_;
    int tid = threadIdx.x, wid = tid >> 5, lane = tid & 31;
    int g = lane >> 2, t = lane & 3;
    int wm = (wid & 3)*32, wn = (wid >> 2)*64;
    int m0 = blockIdx.y*128, n0 = blockIdx.x*128;

    GEMM_MAINLOOP(A, Bm, K_)

    // ---- stage fp32 tile to smem ----
    __syncthreads();
    float* Es = (float*)smh;
    #pragma unroll
    for (int mf = 0; mf < 2; mf++) {
        #pragma unroll
        for (int nf = 0; nf < 8; nf++) {
            int row = wm + mf*16 + g;
            int col = wn + nf*8 + 2*t;
            *(float2*)&Es[row*ESTR + col]     = make_float2(acc[mf][nf][0], acc[mf][nf][1]);
            *(float2*)&Es[(row+8)*ESTR + col] = make_float2(acc[mf][nf][2], acc[mf][nf][3]);
        }
    }
    __syncthreads();

    int bb = m0 >> 11;
    int sbase = m0 & (S_-1);

    if (n0 < 2048) {
        // Q: rotary (xs scale), folded sw*log2e, layout [B,H,S,D]
        const float swq = 0.08838834764831845f * 1.4426950408889634f;
        int h = n0 >> 7;
        size_t obase = (size_t)(bb*H_ + h) * S_;
        int d = tid & 63, rh = tid >> 6;       // rh 0..3
        for (int it = 0; it < 32; it++) {
            int r = rh + it*4;
            float x1 = Es[r*ESTR + d];
            float x2 = Es[r*ESTR + d + 64];
            int s = sbase + r;
            float c = g_qc[s*64+d], sn = g_qs[s*64+d];
            size_t ob = (obase + s)*DH_;
            g_Qh[ob + d]      = __float2half_rn(swq*(x1*c - x2*sn));
            g_Qh[ob + d + 64] = __float2half_rn(swq*(x2*c + x1*sn));
        }
    } else if (n0 == 2048) {
        // K: rotary (1/xs scale), folded sw, layout [B,S,D]
        const float sw = 0.08838834764831845f;
        int d = tid & 63, rh = tid >> 6;
        for (int it = 0; it < 32; it++) {
            int r = rh + it*4;
            float x1 = Es[r*ESTR + d];
            float x2 = Es[r*ESTR + d + 64];
            int s = sbase + r;
            float c = g_kc[s*64+d], sn = g_ks[s*64+d];
            size_t ob = ((size_t)(bb*S_ + s))*DH_;
            g_Kh[ob + d]      = __float2half_rn(sw*(x1*c - x2*sn));
            g_Kh[ob + d + 64] = __float2half_rn(sw*(x2*c + x1*sn));
        }
    } else {
        // V: transpose to [B,D,S]
        int r = tid & 127, dh = tid >> 7;      // dh 0..1
        for (int d2 = 0; d2 < 64; d2++) {
            int d = dh*64 + d2;
            g_Vt[((size_t)(bb*DH_ + d))*S_ + sbase + r] =
                __float2half_rn(Es[r*ESTR + d]);
        }
    }
}

// ========== proj GEMM: out(f32) = ctx @ Wp^T + bias =========================
__global__ __launch_bounds__(256, 2) void gemm_h(
        const __half* __restrict__ A, const __half* __restrict__ Bm,
        float* __restrict__ C, int M, int N, int K_,
        const float* __restrict__ bias) {
    extern __shared__ __half smh[];
    int tid = threadIdx.x, wid = tid >> 5, lane = tid & 31;
    int g = lane >> 2, t = lane & 3;
    int wm = (wid & 3)*32, wn = (wid >> 2)*64;
    int m0 = blockIdx.y*128, n0 = blockIdx.x*128;

    GEMM_MAINLOOP(A, Bm, K_)

    #pragma unroll
    for (int mf = 0; mf < 2; mf++) {
        #pragma unroll
        for (int nf = 0; nf < 8; nf++) {
            int row = m0 + wm + mf*16 + g;
            int col = n0 + wn + nf*8 + 2*t;
            float b0 = bias[col], b1 = bias[col+1];
            *(float2*)&C[(size_t)row*N + col] =
                make_float2(acc[mf][nf][0]+b0, acc[mf][nf][1]+b1);
            *(float2*)&C[(size_t)(row+8)*N + col] =
                make_float2(acc[mf][nf][2]+b0, acc[mf][nf][3]+b1);
        }
    }
}

// ---------------- flash attention (fp16 mma, f16x2 softmax, mma row-sum) ---
#define KS_H (128*136)
#define VS_H (128*136)
#define FSTG_H (KS_H + VS_H)
#define FL_SMEM (2*FSTG_H*2)

__global__ __launch_bounds__(256) void flash_attn() {
    extern __shared__ __half smf[];
    int tid = threadIdx.x;
    int wid = tid >> 5, lane = tid & 31;
    int g = lane >> 2, t = lane & 3;
    int bh = blockIdx.y, b = bh >> 4, h = bh & 15;
    int qt = gridDim.x - 1 - blockIdx.x;   // longest work first
    int q0 = qt * 128;
    int wrow = wid * 16;
    const __half* Qb  = g_Qh + (size_t)bh * S_ * DH_;
    const __half* Kb  = g_Kh + (size_t)b  * S_ * DH_;
    const __half* Vtb = g_Vt + (size_t)b  * DH_ * S_;

    uint32_t smfb = smem_u32(smf);
    uint32_t bmap = ((((lane >> 4)<<3) + (lane & 7))*136 + ((lane >> 3)&1)*8)*2;
    const unsigned ONES2 = 0x3C003C00u;    // f16x2 {1.0, 1.0}

    unsigned qa[8][4];
    {
        int r0 = q0 + wrow + g;
        #pragma unroll
        for (int kb = 0; kb < 8; kb++) {
            int c0 = kb*16 + 2*t;
            qa[kb][0] = *(const unsigned*)&Qb[(size_t)r0*DH_ + c0];
            qa[kb][1] = *(const unsigned*)&Qb[(size_t)(r0+8)*DH_ + c0];
            qa[kb][2] = *(const unsigned*)&Qb[(size_t)r0*DH_ + c0 + 8];
            qa[kb][3] = *(const unsigned*)&Qb[(size_t)(r0+8)*DH_ + c0 + 8];
        }
    }
    float oacc[16][4];
    #pragma unroll
    for (int i=0;i<16;i++)
        #pragma unroll
        for (int j=0;j<4;j++) oacc[i][j]=0.f;
    float mrow[2] = {-1e30f,-1e30f}, lrow[2] = {0.f,0.f};

    int ntiles = qt + 1;
    #define LOAD_KV(stg, j0) do {                                             \
        __half* Ks_ = smf + (stg)*FSTG_H;                                     \
        __half* Vs_ = Ks_ + KS_H;                                             \
        _Pragma("unroll")                                                     \
        for (int it = 0; it < 8; it++) {                                      \
            int idx = tid + it*256;                                           \
            int r = idx >> 4, c = idx & 15;                                   \
            cpasync16(&Ks_[r*136 + c*8], &Kb[(size_t)((j0)+r)*DH_ + c*8]);    \
        }                                                                     \
        _Pragma("unroll")                                                     \
        for (int it = 0; it < 8; it++) {                                      \
            int idx = tid + it*256;                                           \
            int r = idx >> 4, c = idx & 15;                                   \
            cpasync16(&Vs_[r*136 + c*8], &Vtb[(size_t)r*S_ + (j0) + c*8]);    \
        }                                                                     \
    } while (0)

    LOAD_KV(0, 0);
    CP_COMMIT();

    for (int kt = 0; kt < ntiles; kt++) {
        if (kt+1 < ntiles) {
            LOAD_KV((kt+1)&1, (kt+1)*128);
            CP_COMMIT();
            CP_WAIT(1);
        } else {
            CP_WAIT(0);
        }
        __syncthreads();
        uint32_t ksu = smfb + (kt&1)*(FSTG_H*2) + bmap;
        uint32_t vsu = ksu + KS_H*2;
        int j0 = kt * 128;

        // S = Q @ K^T : software-pipelined LDSM (one always in flight)
        float s[16][4];
        #pragma unroll
        for (int i=0;i<16;i++)
            #pragma unroll
            for (int j=0;j<4;j++) s[i][j]=0.f;
        {
            unsigned pf0,pf1,pf2,pf3;
            LDSM4(pf0,pf1,pf2,pf3, ksu);
            #pragma unroll
            for (int i = 0; i < 64; i++) {
                unsigned c0=pf0, c1=pf1, c2=pf2, c3=pf3;
                if (i < 63) {
                    int j = i + 1;
                    LDSM4(pf0,pf1,pf2,pf3, ksu + (j&7)*(16*272) + (j>>3)*32);
                }
                unsigned bb0[2] = {c0,c1}, bb1[2] = {c2,c3};
                int nf2 = i & 7, kb = i >> 3;
                mma_h(s[2*nf2],   qa[kb], bb0);
                mma_h(s[2*nf2+1], qa[kb], bb1);
            }
        }
        // causal mask (diagonal tile only)
        if (kt == ntiles-1) {
            int r0 = q0 + wrow + g;
            #pragma unroll
            for (int nf = 0; nf < 16; nf++) {
                int c0 = j0 + nf*8 + 2*t;
                if (c0   > r0)   s[nf][0] = -1e30f;
                if (c0+1 > r0)   s[nf][1] = -1e30f;
                if (c0   > r0+8) s[nf][2] = -1e30f;
                if (c0+1 > r0+8) s[nf][3] = -1e30f;
            }
        }
        // online softmax, log2 domain: max + rescale only (exp moved to f16x2)
        float corr[2];
        #pragma unroll
        for (int rr = 0; rr < 2; rr++) {
            float mx = -1e30f;
            #pragma unroll
            for (int nf = 0; nf < 16; nf++)
                mx = fmaxf(mx, fmaxf(s[nf][2*rr], s[nf][2*rr+1]));
            mx = fmaxf(mx, __shfl_xor_sync(0xffffffffu, mx, 1));
            mx = fmaxf(mx, __shfl_xor_sync(0xffffffffu, mx, 2));
            float mn = fmaxf(mrow[rr], mx);
            corr[rr] = exp2f(mrow[rr] - mn);
            mrow[rr] = mn;
            #pragma unroll
            for (int nf = 0; nf < 16; nf++) {
                oacc[nf][2*rr]   *= corr[rr];
                oacc[nf][2*rr+1] *= corr[rr];
            }
        }
        // O += P @ V; P = ex2.f16x2(s - m) built in-loop; row-sum via mma vs ones
        float racc[4] = {0.f, 0.f, 0.f, 0.f};
        {
            float mn0 = mrow[0], mn1 = mrow[1];
            unsigned pf0,pf1,pf2,pf3;
            LDSM4(pf0,pf1,pf2,pf3, vsu);
            unsigned pa[4];
            unsigned onesb[2] = {ONES2, ONES2};
            #pragma unroll
            for (int i = 0; i < 64; i++) {
                int nf2 = i & 7, kb2 = i >> 3;
                if (nf2 == 0) {
                    pa[0] = ex2_h2(cvt_h2(s[2*kb2][1]   - mn0, s[2*kb2][0]   - mn0));
                    pa[1] = ex2_h2(cvt_h2(s[2*kb2][3]   - mn1, s[2*kb2][2]   - mn1));
                    pa[2] = ex2_h2(cvt_h2(s[2*kb2+1][1] - mn0, s[2*kb2+1][0] - mn0));
                    pa[3] = ex2_h2(cvt_h2(s[2*kb2+1][3] - mn1, s[2*kb2+1][2] - mn1));
                    mma_h(racc, pa, onesb);
                }
                unsigned c0=pf0, c1=pf1, c2=pf2, c3=pf3;
                if (i < 63) {
                    int j = i + 1;
                    LDSM4(pf0,pf1,pf2,pf3, vsu + (j&7)*(16*272) + (j>>3)*32);
                }
                unsigned bb0[2] = {c0,c1}, bb1[2] = {c2,c3};
                mma_h(oacc[2*nf2],   pa, bb0);
                mma_h(oacc[2*nf2+1], pa, bb1);
            }
        }
        lrow[0] = lrow[0]*corr[0] + racc[0];
        lrow[1] = lrow[1]*corr[1] + racc[2];
        __syncthreads();
    }
    #pragma unroll
    for (int rr = 0; rr < 2; rr++) {
        float inv = 1.f / lrow[rr];
        int row = q0 + wrow + g + 8*rr;
        size_t base = ((size_t)(b*S_ + row))*DM_ + h*DH_;
        #pragma unroll
        for (int nf = 0; nf < 16; nf++) {
            __half2 hv = __floats2half2_rn(oacc[nf][2*rr]*inv, oacc[nf][2*rr+1]*inv);
            *(__half2*)&g_ctxh[base + nf*8 + 2*t] = hv;
        }
    }
    #undef LOAD_KV
}

// ---------------- launch ----------------
extern "C" void kernel_launch(void* const* d_in, const int* in_sizes, int n_in,
                              void* d_out, int out_size) {
    const float* X     = (const float*)d_in[0];
    const float* Wq    = (const float*)d_in[1];
    const float* Wkv   = (const float*)d_in[2];
    const float* Wproj = (const float*)d_in[3];
    const float* bproj = (const float*)d_in[4];
    float* out = (float*)d_out;

    static int attr_set = 0;
    if (!attr_set) {
        cudaFuncSetAttribute(flash_attn, cudaFuncAttributeMaxDynamicSharedMemorySize, FL_SMEM);
        cudaFuncSetAttribute(gemm_h,     cudaFuncAttributeMaxDynamicSharedMemorySize, G_SMEM);
        cudaFuncSetAttribute(gemm_qkv,   cudaFuncAttributeMaxDynamicSharedMemorySize, G_SMEM);
        attr_set = 1;
    }

    __half* ctxh; cudaGetSymbolAddress((void**)&ctxh, g_ctxh);
    __half* wph;  cudaGetSymbolAddress((void**)&wph,  g_Wph);

    const int M = B_*S_;   // 4096

    prep_all<<<CVT_BLOCKS + ROT_BLOCKS, 256>>>((const float4*)X, (const float4*)Wq,
                                               (const float4*)Wkv, (const float4*)Wproj);
    gemm_qkv<<<dim3(NQKV/128, M/128), 256, G_SMEM>>>();
    flash_attn<<<dim3(S_/128, B_*H_), 256, FL_SMEM>>>();
    gemm_h<<<dim3(DM_/128, M/128), 256, G_SMEM>>>(ctxh, wph, out, M, DM_, DM_, bproj);
}